// round 4
// baseline (speedup 1.0000x reference)
#include <cuda_runtime.h>
#include <math.h>

// Problem shapes (fixed by the dataset)
#define NB 4
#define NT 1024
#define ND 512
#define NH 8
#define NDH 64
#define NR 2047          // 2*T - 1
#define NM 4096          // B*T

#define PADK 36          // pad for [row][k=32] tiles
#define PADD 68          // pad for [row][d=64] tiles

// ---------------- device scratch (no allocations allowed) ----------------
__device__ float gQ[NM * ND];
__device__ float gK[NM * ND];
__device__ float gV[NM * ND];
__device__ float gPE[NR * ND];
__device__ float gE[NR * ND];
__device__ float gO[NM * ND];
__device__ float gUK[NB * NH * NT];
__device__ float gVE[NH * NR];

// ---------------- tf32 helpers ----------------
__device__ __forceinline__ unsigned f2tf(float f) {
    unsigned r; asm("cvt.rna.tf32.f32 %0,%1;" : "=r"(r) : "f"(f)); return r;
}
__device__ __forceinline__ void cvt_pair(float f, unsigned& hi, unsigned& lo) {
    hi = f2tf(f);
    lo = f2tf(f - __uint_as_float(hi));
}
__device__ __forceinline__ void mma8(float (&c)[4], unsigned a0, unsigned a1,
                                     unsigned a2, unsigned a3, unsigned b0, unsigned b1) {
    asm volatile(
        "mma.sync.aligned.m16n8k8.row.col.f32.tf32.tf32.f32 "
        "{%0,%1,%2,%3},{%4,%5,%6,%7},{%8,%9},{%0,%1,%2,%3};"
        : "+f"(c[0]), "+f"(c[1]), "+f"(c[2]), "+f"(c[3])
        : "r"(a0), "r"(a1), "r"(a2), "r"(a3), "r"(b0), "r"(b1));
}

// ---------------- positional encoding ----------------
__global__ void pe_kernel() {
    int idx = blockIdx.x * 256 + threadIdx.x;
    if (idx >= NR * 256) return;
    int r = idx >> 8;
    int m = idx & 255;
    double inv = exp(-((double)(2 * m) / 512.0) * log(10000.0));
    double ang = (double)(1023 - r) * inv;
    gPE[r * ND + 2 * m]     = (float)sin(ang);
    gPE[r * ND + 2 * m + 1] = (float)cos(ang);
}

// ---------------- C[M,512] = A[M,512] @ W[512,512]^T + bias (3xTF32) ------
__global__ void proj_tc(const float* __restrict__ A, const float* __restrict__ W,
                        const float* __restrict__ bias, float* __restrict__ C, int M) {
    extern __shared__ unsigned sm[];
    unsigned* Ah = sm;                    // 128*PADK
    unsigned* Al = Ah + 128 * PADK;
    unsigned* Wh = Al + 128 * PADK;       // 64*PADK, stored [n][k]
    unsigned* Wl = Wh + 64 * PADK;
    int tid = threadIdx.x;
    int warp = tid >> 5, lane = tid & 31;
    int wm = warp >> 1, wn = warp & 1;
    int g = lane >> 2, t = lane & 3;
    int bm = blockIdx.y * 128, bn = blockIdx.x * 64;
    float acc[2][4][4] = {};

    for (int k0 = 0; k0 < 512; k0 += 32) {
        #pragma unroll
        for (int i = 0; i < 4; i++) {
            int idx = tid + i * 256;
            int row = idx >> 3, c4 = (idx & 7) << 2;
            int grow = bm + row;
            float4 av = (grow < M) ? *(const float4*)&A[(size_t)grow * 512 + k0 + c4]
                                   : make_float4(0.f, 0.f, 0.f, 0.f);
            float a4[4] = {av.x, av.y, av.z, av.w};
            #pragma unroll
            for (int j = 0; j < 4; j++)
                cvt_pair(a4[j], Ah[row * PADK + c4 + j], Al[row * PADK + c4 + j]);
        }
        #pragma unroll
        for (int i = 0; i < 2; i++) {
            int idx = tid + i * 256;
            int row = idx >> 3, c4 = (idx & 7) << 2;
            float4 wv = *(const float4*)&W[(size_t)(bn + row) * 512 + k0 + c4];
            float w4[4] = {wv.x, wv.y, wv.z, wv.w};
            #pragma unroll
            for (int j = 0; j < 4; j++)
                cvt_pair(w4[j], Wh[row * PADK + c4 + j], Wl[row * PADK + c4 + j]);
        }
        __syncthreads();
        #pragma unroll
        for (int kk = 0; kk < 32; kk += 8) {
            unsigned ah[2][4], al[2][4];
            #pragma unroll
            for (int mt = 0; mt < 2; mt++) {
                int ar = wm * 32 + mt * 16 + g;
                ah[mt][0] = Ah[ar * PADK + kk + t];
                ah[mt][1] = Ah[(ar + 8) * PADK + kk + t];
                ah[mt][2] = Ah[ar * PADK + kk + t + 4];
                ah[mt][3] = Ah[(ar + 8) * PADK + kk + t + 4];
                al[mt][0] = Al[ar * PADK + kk + t];
                al[mt][1] = Al[(ar + 8) * PADK + kk + t];
                al[mt][2] = Al[ar * PADK + kk + t + 4];
                al[mt][3] = Al[(ar + 8) * PADK + kk + t + 4];
            }
            #pragma unroll
            for (int nt = 0; nt < 4; nt++) {
                int nb = wn * 32 + nt * 8 + g;
                unsigned bh0 = Wh[nb * PADK + kk + t], bh1 = Wh[nb * PADK + kk + t + 4];
                unsigned bl0 = Wl[nb * PADK + kk + t], bl1 = Wl[nb * PADK + kk + t + 4];
                #pragma unroll
                for (int mt = 0; mt < 2; mt++) {
                    mma8(acc[mt][nt], ah[mt][0], ah[mt][1], ah[mt][2], ah[mt][3], bh0, bh1);
                    mma8(acc[mt][nt], ah[mt][0], ah[mt][1], ah[mt][2], ah[mt][3], bl0, bl1);
                    mma8(acc[mt][nt], al[mt][0], al[mt][1], al[mt][2], al[mt][3], bh0, bh1);
                }
            }
        }
        __syncthreads();
    }
    #pragma unroll
    for (int mt = 0; mt < 2; mt++) {
        #pragma unroll
        for (int nt = 0; nt < 4; nt++) {
            int row = bm + wm * 32 + mt * 16 + g;
            int col = bn + wn * 32 + nt * 8 + t * 2;
            if (row < M) {
                C[(size_t)row * 512 + col]     = acc[mt][nt][0] + bias[col];
                C[(size_t)row * 512 + col + 1] = acc[mt][nt][1] + bias[col + 1];
            }
            if (row + 8 < M) {
                C[(size_t)(row + 8) * 512 + col]     = acc[mt][nt][2] + bias[col];
                C[(size_t)(row + 8) * 512 + col + 1] = acc[mt][nt][3] + bias[col + 1];
            }
        }
    }
}

// ---------------- gUK / gVE -------------------------------------------
__global__ void uk_kernel(const float* __restrict__ u) {
    int gid = blockIdx.x * 256 + threadIdx.x;
    int w = gid >> 5, lane = gid & 31;
    if (w >= NB * NH * NT) return;
    int t = w & (NT - 1);
    int bh = w >> 10;
    int h = bh & 7, b = bh >> 3;
    const float* kp = gK + (size_t)(b * NT + t) * ND + h * NDH;
    const float* up = u + h * NDH;
    float s = kp[lane] * up[lane] + kp[lane + 32] * up[lane + 32];
    #pragma unroll
    for (int o = 16; o; o >>= 1) s += __shfl_down_sync(0xffffffffu, s, o);
    if (lane == 0) gUK[bh * NT + t] = s;
}

__global__ void ve_kernel(const float* __restrict__ v) {
    int gid = blockIdx.x * 256 + threadIdx.x;
    int w = gid >> 5, lane = gid & 31;
    if (w >= NH * NR) return;
    int h = w / NR;
    int r = w - h * NR;
    const float* ep = gE + (size_t)r * ND + h * NDH;
    const float* vp = v + h * NDH;
    float s = ep[lane] * vp[lane] + ep[lane + 32] * vp[lane + 32];
    #pragma unroll
    for (int o = 16; o; o >>= 1) s += __shfl_down_sync(0xffffffffu, s, o);
    if (lane == 0) gVE[h * NR + r] = s;
}

// ---------------- fused flash attention (3xTF32 mma) ---------------------
// One block per (bh, q-tile of 64). Streams 16 k-tiles of 64:
//   S = Q.K^T + skewed-E-gather + uK + vE, online softmax, acc += P.V
// 256 thr, warps 4m x 2n; warp tile 16x32; per-thread 2 rows x 8 cols.
__global__ void flash_tc() {
    extern __shared__ unsigned sm[];
    unsigned* Qh  = sm;                    // 64*PADD
    unsigned* Ql  = Qh  + 64 * PADD;
    unsigned* Bh  = Ql  + 64 * PADD;       // K tile then E chunks, [n][k=d]
    unsigned* Bl  = Bh  + 64 * PADD;
    unsigned* Vth = Bl  + 64 * PADD;       // V^T tile [d][pos]
    unsigned* Vtl = Vth + 64 * PADD;
    unsigned* U   = Vtl + 64 * PADD;       // union: Gs (64*132 fl) | Ph+Pl
    float*    Gs  = (float*)U;
    unsigned* Ph  = U;
    unsigned* Pl  = Ph + 64 * PADD;
    float*    redM = (float*)(U + 2 * 64 * PADD);  // [2][64]
    float*    redL = redM + 128;                   // [2][64]

    int tid = threadIdx.x;
    int bh = blockIdx.y, h = bh & 7, b = bh >> 3;
    int q0 = blockIdx.x * 64;
    int warp = tid >> 5, lane = tid & 31;
    int wm = warp >> 1, wn = warp & 1;
    int g = lane >> 2, t = lane & 3;
    int row0 = wm * 16 + g;                // this thread's first q row (second: +8)

    // ---- load Q tile once ----
    #pragma unroll
    for (int i = 0; i < 4; i++) {
        int idx = tid + i * 256;
        int row = idx >> 4, c4 = (idx & 15) << 2;
        float4 qv = *(const float4*)&gQ[(size_t)(b * NT + q0 + row) * ND + h * NDH + c4];
        float q4[4] = {qv.x, qv.y, qv.z, qv.w};
        #pragma unroll
        for (int j = 0; j < 4; j++)
            cvt_pair(q4[j], Qh[row * PADD + c4 + j], Ql[row * PADD + c4 + j]);
    }

    float accO[4][4] = {};
    float mOld0 = -1e30f, mOld1 = -1e30f;
    float lRun0 = 0.f, lRun1 = 0.f;

    for (int kt = 0; kt < 16; kt++) {
        int k0 = kt * 64;
        __syncthreads();   // prev tile's PV reads of Ph/Vth, E reads of Bh done

        // ---- load K tile -> Bh/Bl, V^T tile -> Vth/Vtl ----
        #pragma unroll
        for (int i = 0; i < 4; i++) {
            int idx = tid + i * 256;
            int row = idx >> 4, c4 = (idx & 15) << 2;
            float4 kv = *(const float4*)&gK[(size_t)(b * NT + k0 + row) * ND + h * NDH + c4];
            float4 vv = *(const float4*)&gV[(size_t)(b * NT + k0 + row) * ND + h * NDH + c4];
            float k4[4] = {kv.x, kv.y, kv.z, kv.w};
            float v4[4] = {vv.x, vv.y, vv.z, vv.w};
            #pragma unroll
            for (int j = 0; j < 4; j++) {
                cvt_pair(k4[j], Bh[row * PADD + c4 + j], Bl[row * PADD + c4 + j]);
                cvt_pair(v4[j], Vth[(c4 + j) * PADD + row], Vtl[(c4 + j) * PADD + row]);
            }
        }
        __syncthreads();

        // ---- S = Q.K^T (3xTF32) ----
        float accK[4][4] = {};
        int ar = row0;
        #pragma unroll
        for (int kk = 0; kk < 64; kk += 8) {
            unsigned ah[4], al[4];
            ah[0] = Qh[ar * PADD + kk + t];       ah[1] = Qh[(ar + 8) * PADD + kk + t];
            ah[2] = Qh[ar * PADD + kk + t + 4];   ah[3] = Qh[(ar + 8) * PADD + kk + t + 4];
            al[0] = Ql[ar * PADD + kk + t];       al[1] = Ql[(ar + 8) * PADD + kk + t];
            al[2] = Ql[ar * PADD + kk + t + 4];   al[3] = Ql[(ar + 8) * PADD + kk + t + 4];
            #pragma unroll
            for (int nt = 0; nt < 4; nt++) {
                int nb = wn * 32 + nt * 8 + g;
                unsigned bh0 = Bh[nb * PADD + kk + t], bh1 = Bh[nb * PADD + kk + t + 4];
                unsigned bl0 = Bl[nb * PADD + kk + t], bl1 = Bl[nb * PADD + kk + t + 4];
                mma8(accK[nt], ah[0], ah[1], ah[2], ah[3], bh0, bh1);
                mma8(accK[nt], ah[0], ah[1], ah[2], ah[3], bl0, bl1);
                mma8(accK[nt], al[0], al[1], al[2], al[3], bh0, bh1);
            }
        }

        // ---- skewed E GEMM in two 64-col chunks -> Gs ----
        int rbase = 960 + k0 - q0;
        #pragma unroll
        for (int chunk = 0; chunk < 2; chunk++) {
            __syncthreads();
            #pragma unroll
            for (int i = 0; i < 4; i++) {
                int idx = tid + i * 256;
                int row = idx >> 4, c4 = (idx & 15) << 2;
                int r = rbase + chunk * 64 + row;
                float4 ev = (r < NR) ? *(const float4*)&gE[(size_t)r * ND + h * NDH + c4]
                                     : make_float4(0.f, 0.f, 0.f, 0.f);
                float e4[4] = {ev.x, ev.y, ev.z, ev.w};
                #pragma unroll
                for (int j = 0; j < 4; j++)
                    cvt_pair(e4[j], Bh[row * PADD + c4 + j], Bl[row * PADD + c4 + j]);
            }
            __syncthreads();
            float accE[4][4] = {};
            #pragma unroll
            for (int kk = 0; kk < 64; kk += 8) {
                unsigned ah[4], al[4];
                ah[0] = Qh[ar * PADD + kk + t];       ah[1] = Qh[(ar + 8) * PADD + kk + t];
                ah[2] = Qh[ar * PADD + kk + t + 4];   ah[3] = Qh[(ar + 8) * PADD + kk + t + 4];
                al[0] = Ql[ar * PADD + kk + t];       al[1] = Ql[(ar + 8) * PADD + kk + t];
                al[2] = Ql[ar * PADD + kk + t + 4];   al[3] = Ql[(ar + 8) * PADD + kk + t + 4];
                #pragma unroll
                for (int nt = 0; nt < 4; nt++) {
                    int nb = wn * 32 + nt * 8 + g;
                    unsigned bh0 = Bh[nb * PADD + kk + t], bh1 = Bh[nb * PADD + kk + t + 4];
                    unsigned bl0 = Bl[nb * PADD + kk + t], bl1 = Bl[nb * PADD + kk + t + 4];
                    mma8(accE[nt], ah[0], ah[1], ah[2], ah[3], bh0, bh1);
                    mma8(accE[nt], ah[0], ah[1], ah[2], ah[3], bl0, bl1);
                    mma8(accE[nt], al[0], al[1], al[2], al[3], bh0, bh1);
                }
            }
            #pragma unroll
            for (int nt = 0; nt < 4; nt++) {
                int col = chunk * 64 + wn * 32 + nt * 8 + t * 2;
                Gs[row0 * 132 + col]           = accE[nt][0];
                Gs[row0 * 132 + col + 1]       = accE[nt][1];
                Gs[(row0 + 8) * 132 + col]     = accE[nt][2];
                Gs[(row0 + 8) * 132 + col + 1] = accE[nt][3];
            }
        }
        __syncthreads();

        // ---- gather full scores into registers ----
        float sv[4][4];
        #pragma unroll
        for (int nt = 0; nt < 4; nt++) {
            int kb = wn * 32 + nt * 8 + t * 2;
            #pragma unroll
            for (int r4 = 0; r4 < 4; r4++) {
                int q = row0 + ((r4 >= 2) ? 8 : 0);
                int k = kb + (r4 & 1);
                int c = k + 63 - q;
                sv[nt][r4] = (accK[nt][r4] + Gs[q * 132 + c]
                              + gUK[bh * NT + k0 + k] + gVE[h * NR + rbase + c]) * 0.125f;
            }
        }

        // ---- online softmax: row max ----
        float m0 = -1e30f, m1 = -1e30f;
        #pragma unroll
        for (int nt = 0; nt < 4; nt++) {
            m0 = fmaxf(m0, fmaxf(sv[nt][0], sv[nt][1]));
            m1 = fmaxf(m1, fmaxf(sv[nt][2], sv[nt][3]));
        }
        m0 = fmaxf(m0, __shfl_xor_sync(0xffffffffu, m0, 1));
        m0 = fmaxf(m0, __shfl_xor_sync(0xffffffffu, m0, 2));
        m1 = fmaxf(m1, __shfl_xor_sync(0xffffffffu, m1, 1));
        m1 = fmaxf(m1, __shfl_xor_sync(0xffffffffu, m1, 2));
        if (t == 0) {
            redM[wn * 64 + row0]     = m0;
            redM[wn * 64 + row0 + 8] = m1;
        }
        __syncthreads();   // also guarantees all Gs reads done before P overwrite
        m0 = fmaxf(redM[row0],     redM[64 + row0]);
        m1 = fmaxf(redM[row0 + 8], redM[64 + row0 + 8]);
        float mn0 = fmaxf(mOld0, m0), mn1 = fmaxf(mOld1, m1);

        // ---- p = exp(s - m), row sums ----
        float sum0 = 0.f, sum1 = 0.f;
        #pragma unroll
        for (int nt = 0; nt < 4; nt++) {
            sv[nt][0] = __expf(sv[nt][0] - mn0);
            sv[nt][1] = __expf(sv[nt][1] - mn0);
            sv[nt][2] = __expf(sv[nt][2] - mn1);
            sv[nt][3] = __expf(sv[nt][3] - mn1);
            sum0 += sv[nt][0] + sv[nt][1];
            sum1 += sv[nt][2] + sv[nt][3];
        }
        sum0 += __shfl_xor_sync(0xffffffffu, sum0, 1);
        sum0 += __shfl_xor_sync(0xffffffffu, sum0, 2);
        sum1 += __shfl_xor_sync(0xffffffffu, sum1, 1);
        sum1 += __shfl_xor_sync(0xffffffffu, sum1, 2);
        if (t == 0) {
            redL[wn * 64 + row0]     = sum0;
            redL[wn * 64 + row0 + 8] = sum1;
        }
        float e0 = __expf(mOld0 - mn0), e1 = __expf(mOld1 - mn1);
        __syncthreads();
        sum0 = redL[row0]     + redL[64 + row0];
        sum1 = redL[row0 + 8] + redL[64 + row0 + 8];
        lRun0 = lRun0 * e0 + sum0;
        lRun1 = lRun1 * e1 + sum1;
        mOld0 = mn0; mOld1 = mn1;
        #pragma unroll
        for (int nt = 0; nt < 4; nt++) {
            accO[nt][0] *= e0; accO[nt][1] *= e0;
            accO[nt][2] *= e1; accO[nt][3] *= e1;
        }

        // ---- write P hi/lo to smem (overwrites Gs region) ----
        #pragma unroll
        for (int nt = 0; nt < 4; nt++) {
            int col = wn * 32 + nt * 8 + t * 2;
            cvt_pair(sv[nt][0], Ph[row0 * PADD + col],           Pl[row0 * PADD + col]);
            cvt_pair(sv[nt][1], Ph[row0 * PADD + col + 1],       Pl[row0 * PADD + col + 1]);
            cvt_pair(sv[nt][2], Ph[(row0 + 8) * PADD + col],     Pl[(row0 + 8) * PADD + col]);
            cvt_pair(sv[nt][3], Ph[(row0 + 8) * PADD + col + 1], Pl[(row0 + 8) * PADD + col + 1]);
        }
        __syncthreads();

        // ---- accO += P.V (3xTF32) ----
        #pragma unroll
        for (int kk = 0; kk < 64; kk += 8) {
            unsigned ah[4], al[4];
            ah[0] = Ph[ar * PADD + kk + t];       ah[1] = Ph[(ar + 8) * PADD + kk + t];
            ah[2] = Ph[ar * PADD + kk + t + 4];   ah[3] = Ph[(ar + 8) * PADD + kk + t + 4];
            al[0] = Pl[ar * PADD + kk + t];       al[1] = Pl[(ar + 8) * PADD + kk + t];
            al[2] = Pl[ar * PADD + kk + t + 4];   al[3] = Pl[(ar + 8) * PADD + kk + t + 4];
            #pragma unroll
            for (int nt = 0; nt < 4; nt++) {
                int nb = wn * 32 + nt * 8 + g;
                unsigned bh0 = Vth[nb * PADD + kk + t], bh1 = Vth[nb * PADD + kk + t + 4];
                unsigned bl0 = Vtl[nb * PADD + kk + t], bl1 = Vtl[nb * PADD + kk + t + 4];
                mma8(accO[nt], ah[0], ah[1], ah[2], ah[3], bh0, bh1);
                mma8(accO[nt], ah[0], ah[1], ah[2], ah[3], bl0, bl1);
                mma8(accO[nt], al[0], al[1], al[2], al[3], bh0, bh1);
            }
        }
    }

    // ---- epilogue: out = acc / l ----
    float inv0 = 1.f / lRun0, inv1 = 1.f / lRun1;
    #pragma unroll
    for (int nt = 0; nt < 4; nt++) {
        int row = q0 + row0;
        int col = wn * 32 + nt * 8 + t * 2;
        float* o0 = &gO[(size_t)(b * NT + row) * ND + h * NDH + col];
        float* o1 = &gO[(size_t)(b * NT + row + 8) * ND + h * NDH + col];
        o0[0] = accO[nt][0] * inv0;  o0[1] = accO[nt][1] * inv0;
        o1[0] = accO[nt][2] * inv1;  o1[1] = accO[nt][3] * inv1;
    }
}

// -------------------------------------------------------------------------
extern "C" void kernel_launch(void* const* d_in, const int* in_sizes, int n_in,
                              void* d_out, int out_size) {
    const float* query = (const float*)d_in[0];
    const float* key_  = (const float*)d_in[1];
    const float* value = (const float*)d_in[2];
    const float* Wq = (const float*)d_in[3];
    const float* bq = (const float*)d_in[4];
    const float* Wk = (const float*)d_in[5];
    const float* bk = (const float*)d_in[6];
    const float* Wv = (const float*)d_in[7];
    const float* bv = (const float*)d_in[8];
    const float* Wp = (const float*)d_in[9];
    const float* bp = (const float*)d_in[10];
    const float* Wo = (const float*)d_in[11];
    const float* bo = (const float*)d_in[12];
    const float* ub = (const float*)d_in[13];
    const float* vb = (const float*)d_in[14];
    float* out = (float*)d_out;

    float *pQ, *pK, *pV, *pPE, *pE, *pO;
    cudaGetSymbolAddress((void**)&pQ, gQ);
    cudaGetSymbolAddress((void**)&pK, gK);
    cudaGetSymbolAddress((void**)&pV, gV);
    cudaGetSymbolAddress((void**)&pPE, gPE);
    cudaGetSymbolAddress((void**)&pE, gE);
    cudaGetSymbolAddress((void**)&pO, gO);

    const int PROJ_SMEM  = (2 * 128 * PADK + 2 * 64 * PADK) * 4;            // 55296
    const int FLASH_SMEM = (6 * 64 * PADD + 2 * 64 * PADD + 256) * 4;       // 140,288
    cudaFuncSetAttribute(proj_tc,  cudaFuncAttributeMaxDynamicSharedMemorySize, PROJ_SMEM);
    cudaFuncSetAttribute(flash_tc, cudaFuncAttributeMaxDynamicSharedMemorySize, FLASH_SMEM);

    pe_kernel<<<NR, 256>>>();
    proj_tc<<<dim3(8, 32), 256, PROJ_SMEM>>>(query, Wq, bq, pQ, NM);
    proj_tc<<<dim3(8, 32), 256, PROJ_SMEM>>>(key_,  Wk, bk, pK, NM);
    proj_tc<<<dim3(8, 32), 256, PROJ_SMEM>>>(value, Wv, bv, pV, NM);
    proj_tc<<<dim3(8, 16), 256, PROJ_SMEM>>>(pPE,   Wp, bp, pE, NR);
    uk_kernel<<<(NB * NH * NT * 32) / 256, 256>>>(ub);
    ve_kernel<<<(NH * NR * 32 + 255) / 256, 256>>>(vb);
    flash_tc<<<dim3(16, 32), 256, FLASH_SMEM>>>();
    proj_tc<<<dim3(8, 32), 256, PROJ_SMEM>>>(pO, Wo, bo, out, NM);
}

// round 5
// speedup vs baseline: 1.5744x; 1.5744x over previous
#include <cuda_runtime.h>
#include <cuda_bf16.h>
#include <math.h>

// Problem shapes (fixed by the dataset)
#define NB 4
#define NT 1024
#define ND 512
#define NH 8
#define NDH 64
#define NR 2047          // 2*T - 1
#define NM 4096          // B*T

#define PW 36            // padded word-row length (32 data words + 4)

// ---------------- device scratch (no allocations allowed) ----------------
__device__ float gQ[NM * ND];
__device__ float gK[NM * ND];
__device__ float gV[NM * ND];
__device__ float gPE[NR * ND];
__device__ float gE[NR * ND];
__device__ float gS[33554432];      // B*H*T*T
__device__ float gO[NM * ND];
__device__ float gUK[NB * NH * NT];
__device__ float gVE[NH * NR];

// ---------------- bf16 split helpers ----------------
// pack two consecutive k-elements into one bf16x2 word (low = even col),
// hi = leading 8 mantissa bits, lo = next 8 (residual).
__device__ __forceinline__ void cvt_pair2(float a, float b, unsigned& hi, unsigned& lo) {
    unsigned ha = __bfloat16_as_ushort(__float2bfloat16(a));
    unsigned hb = __bfloat16_as_ushort(__float2bfloat16(b));
    float ra = a - __bfloat162float(__ushort_as_bfloat16((unsigned short)ha));
    float rb = b - __bfloat162float(__ushort_as_bfloat16((unsigned short)hb));
    unsigned la = __bfloat16_as_ushort(__float2bfloat16(ra));
    unsigned lb = __bfloat16_as_ushort(__float2bfloat16(rb));
    hi = (hb << 16) | ha;
    lo = (lb << 16) | la;
}
__device__ __forceinline__ void mma16(float (&c)[4], unsigned a0, unsigned a1,
                                      unsigned a2, unsigned a3, unsigned b0, unsigned b1) {
    asm volatile(
        "mma.sync.aligned.m16n8k16.row.col.f32.bf16.bf16.f32 "
        "{%0,%1,%2,%3},{%4,%5,%6,%7},{%8,%9},{%0,%1,%2,%3};"
        : "+f"(c[0]), "+f"(c[1]), "+f"(c[2]), "+f"(c[3])
        : "r"(a0), "r"(a1), "r"(a2), "r"(a3), "r"(b0), "r"(b1));
}

// ---------------- positional encoding ----------------
__global__ void pe_kernel() {
    int idx = blockIdx.x * 256 + threadIdx.x;
    if (idx >= NR * 256) return;
    int r = idx >> 8;
    int m = idx & 255;
    double inv = exp(-((double)(2 * m) / 512.0) * log(10000.0));
    double ang = (double)(1023 - r) * inv;
    gPE[r * ND + 2 * m]     = (float)sin(ang);
    gPE[r * ND + 2 * m + 1] = (float)cos(ang);
}

// ---------------- C[M,512] = A[M,512] @ W[512,512]^T + bias (3xBF16) ------
// Block: 256 thr (8 warps, 4m x 2n), tile 128x64, k-chunk 64 cols = 32 words.
__global__ void proj_tc(const float* __restrict__ A, const float* __restrict__ W,
                        const float* __restrict__ bias, float* __restrict__ C, int M) {
    extern __shared__ unsigned sm[];
    unsigned* Ah = sm;                    // 128*PW
    unsigned* Al = Ah + 128 * PW;
    unsigned* Wh = Al + 128 * PW;         // 64*PW, stored [n][kword]
    unsigned* Wl = Wh + 64 * PW;
    int tid = threadIdx.x;
    int warp = tid >> 5, lane = tid & 31;
    int wm = warp >> 1, wn = warp & 1;
    int g = lane >> 2, t = lane & 3;
    int bm = blockIdx.y * 128, bn = blockIdx.x * 64;
    float acc[2][4][4] = {};

    for (int k0 = 0; k0 < 512; k0 += 64) {
        #pragma unroll
        for (int i = 0; i < 8; i++) {
            int idx = tid + i * 256;
            int row = idx >> 4, c4 = (idx & 15) << 2;
            int grow = bm + row;
            float4 av = (grow < M) ? *(const float4*)&A[(size_t)grow * 512 + k0 + c4]
                                   : make_float4(0.f, 0.f, 0.f, 0.f);
            int w = c4 >> 1;
            cvt_pair2(av.x, av.y, Ah[row * PW + w],     Al[row * PW + w]);
            cvt_pair2(av.z, av.w, Ah[row * PW + w + 1], Al[row * PW + w + 1]);
        }
        #pragma unroll
        for (int i = 0; i < 4; i++) {
            int idx = tid + i * 256;
            int row = idx >> 4, c4 = (idx & 15) << 2;
            float4 wv = *(const float4*)&W[(size_t)(bn + row) * 512 + k0 + c4];
            int w = c4 >> 1;
            cvt_pair2(wv.x, wv.y, Wh[row * PW + w],     Wl[row * PW + w]);
            cvt_pair2(wv.z, wv.w, Wh[row * PW + w + 1], Wl[row * PW + w + 1]);
        }
        __syncthreads();
        #pragma unroll
        for (int kw = 0; kw < 32; kw += 8) {
            unsigned ah[2][4], al[2][4];
            #pragma unroll
            for (int mt = 0; mt < 2; mt++) {
                int ar = wm * 32 + mt * 16 + g;
                ah[mt][0] = Ah[ar * PW + kw + t];
                ah[mt][1] = Ah[(ar + 8) * PW + kw + t];
                ah[mt][2] = Ah[ar * PW + kw + t + 4];
                ah[mt][3] = Ah[(ar + 8) * PW + kw + t + 4];
                al[mt][0] = Al[ar * PW + kw + t];
                al[mt][1] = Al[(ar + 8) * PW + kw + t];
                al[mt][2] = Al[ar * PW + kw + t + 4];
                al[mt][3] = Al[(ar + 8) * PW + kw + t + 4];
            }
            #pragma unroll
            for (int nt = 0; nt < 4; nt++) {
                int nb = wn * 32 + nt * 8 + g;
                unsigned bh0 = Wh[nb * PW + kw + t], bh1 = Wh[nb * PW + kw + t + 4];
                unsigned bl0 = Wl[nb * PW + kw + t], bl1 = Wl[nb * PW + kw + t + 4];
                #pragma unroll
                for (int mt = 0; mt < 2; mt++) {
                    mma16(acc[mt][nt], ah[mt][0], ah[mt][1], ah[mt][2], ah[mt][3], bh0, bh1);
                    mma16(acc[mt][nt], ah[mt][0], ah[mt][1], ah[mt][2], ah[mt][3], bl0, bl1);
                    mma16(acc[mt][nt], al[mt][0], al[mt][1], al[mt][2], al[mt][3], bh0, bh1);
                }
            }
        }
        __syncthreads();
    }
    #pragma unroll
    for (int mt = 0; mt < 2; mt++) {
        #pragma unroll
        for (int nt = 0; nt < 4; nt++) {
            int row = bm + wm * 32 + mt * 16 + g;
            int col = bn + wn * 32 + nt * 8 + t * 2;
            if (row < M) {
                C[(size_t)row * 512 + col]     = acc[mt][nt][0] + bias[col];
                C[(size_t)row * 512 + col + 1] = acc[mt][nt][1] + bias[col + 1];
            }
            if (row + 8 < M) {
                C[(size_t)(row + 8) * 512 + col]     = acc[mt][nt][2] + bias[col];
                C[(size_t)(row + 8) * 512 + col + 1] = acc[mt][nt][3] + bias[col + 1];
            }
        }
    }
}

// ---------------- gUK / gVE -------------------------------------------
__global__ void uk_kernel(const float* __restrict__ u) {
    int gid = blockIdx.x * 256 + threadIdx.x;
    int w = gid >> 5, lane = gid & 31;
    if (w >= NB * NH * NT) return;
    int t = w & (NT - 1);
    int bh = w >> 10;
    int h = bh & 7, b = bh >> 3;
    const float* kp = gK + (size_t)(b * NT + t) * ND + h * NDH;
    const float* up = u + h * NDH;
    float s = kp[lane] * up[lane] + kp[lane + 32] * up[lane + 32];
    #pragma unroll
    for (int o = 16; o; o >>= 1) s += __shfl_down_sync(0xffffffffu, s, o);
    if (lane == 0) gUK[bh * NT + t] = s;
}

__global__ void ve_kernel(const float* __restrict__ v) {
    int gid = blockIdx.x * 256 + threadIdx.x;
    int w = gid >> 5, lane = gid & 31;
    if (w >= NH * NR) return;
    int h = w / NR;
    int r = w - h * NR;
    const float* ep = gE + (size_t)r * ND + h * NDH;
    const float* vp = v + h * NDH;
    float s = ep[lane] * vp[lane] + ep[lane + 32] * vp[lane + 32];
    #pragma unroll
    for (int o = 16; o; o >>= 1) s += __shfl_down_sync(0xffffffffu, s, o);
    if (lane == 0) gVE[h * NR + r] = s;
}

// ---------------- scores (tensor, 3xBF16) --------------------------------
// 64x64 tile per block, 256 thr, warps 4m x 2n (warp tile 16x32).
__global__ void scores_tc() {
    extern __shared__ unsigned sm[];
    unsigned* Qh = sm;                    // 64*PW
    unsigned* Ql = Qh + 64 * PW;
    unsigned* Bh = Ql + 64 * PW;          // K tile then E chunks, [n][dword]
    unsigned* Bl = Bh + 64 * PW;
    float* Gs = (float*)(Bl + 64 * PW);   // 64*132
    int tid = threadIdx.x;
    int bh = blockIdx.z, h = bh & 7, b = bh >> 3;
    int q0 = blockIdx.y * 64, k0 = blockIdx.x * 64;
    int warp = tid >> 5, lane = tid & 31;
    int wm = warp >> 1, wn = warp & 1;
    int g = lane >> 2, t = lane & 3;

    #pragma unroll
    for (int i = 0; i < 4; i++) {
        int idx = tid + i * 256;
        int row = idx >> 4, c4 = (idx & 15) << 2;
        float4 qv = *(const float4*)&gQ[(size_t)(b * NT + q0 + row) * ND + h * NDH + c4];
        float4 kv = *(const float4*)&gK[(size_t)(b * NT + k0 + row) * ND + h * NDH + c4];
        int w = c4 >> 1;
        cvt_pair2(qv.x, qv.y, Qh[row * PW + w],     Ql[row * PW + w]);
        cvt_pair2(qv.z, qv.w, Qh[row * PW + w + 1], Ql[row * PW + w + 1]);
        cvt_pair2(kv.x, kv.y, Bh[row * PW + w],     Bl[row * PW + w]);
        cvt_pair2(kv.z, kv.w, Bh[row * PW + w + 1], Bl[row * PW + w + 1]);
    }
    __syncthreads();

    float accK[4][4] = {};
    int ar = wm * 16 + g;
    #pragma unroll
    for (int kw = 0; kw < 32; kw += 8) {
        unsigned ah[4], al[4];
        ah[0] = Qh[ar * PW + kw + t];       ah[1] = Qh[(ar + 8) * PW + kw + t];
        ah[2] = Qh[ar * PW + kw + t + 4];   ah[3] = Qh[(ar + 8) * PW + kw + t + 4];
        al[0] = Ql[ar * PW + kw + t];       al[1] = Ql[(ar + 8) * PW + kw + t];
        al[2] = Ql[ar * PW + kw + t + 4];   al[3] = Ql[(ar + 8) * PW + kw + t + 4];
        #pragma unroll
        for (int nt = 0; nt < 4; nt++) {
            int nb = wn * 32 + nt * 8 + g;
            unsigned bh0 = Bh[nb * PW + kw + t], bh1 = Bh[nb * PW + kw + t + 4];
            unsigned bl0 = Bl[nb * PW + kw + t], bl1 = Bl[nb * PW + kw + t + 4];
            mma16(accK[nt], ah[0], ah[1], ah[2], ah[3], bh0, bh1);
            mma16(accK[nt], ah[0], ah[1], ah[2], ah[3], bl0, bl1);
            mma16(accK[nt], al[0], al[1], al[2], al[3], bh0, bh1);
        }
    }

    int rbase = 960 + k0 - q0;   // >= 0 always
    for (int chunk = 0; chunk < 2; chunk++) {
        __syncthreads();
        #pragma unroll
        for (int i = 0; i < 4; i++) {
            int idx = tid + i * 256;
            int row = idx >> 4, c4 = (idx & 15) << 2;
            int r = rbase + chunk * 64 + row;
            float4 ev = (r < NR) ? *(const float4*)&gE[(size_t)r * ND + h * NDH + c4]
                                 : make_float4(0.f, 0.f, 0.f, 0.f);
            int w = c4 >> 1;
            cvt_pair2(ev.x, ev.y, Bh[row * PW + w],     Bl[row * PW + w]);
            cvt_pair2(ev.z, ev.w, Bh[row * PW + w + 1], Bl[row * PW + w + 1]);
        }
        __syncthreads();
        float accE[4][4] = {};
        #pragma unroll
        for (int kw = 0; kw < 32; kw += 8) {
            unsigned ah[4], al[4];
            ah[0] = Qh[ar * PW + kw + t];       ah[1] = Qh[(ar + 8) * PW + kw + t];
            ah[2] = Qh[ar * PW + kw + t + 4];   ah[3] = Qh[(ar + 8) * PW + kw + t + 4];
            al[0] = Ql[ar * PW + kw + t];       al[1] = Ql[(ar + 8) * PW + kw + t];
            al[2] = Ql[ar * PW + kw + t + 4];   al[3] = Ql[(ar + 8) * PW + kw + t + 4];
            #pragma unroll
            for (int nt = 0; nt < 4; nt++) {
                int nb = wn * 32 + nt * 8 + g;
                unsigned bh0 = Bh[nb * PW + kw + t], bh1 = Bh[nb * PW + kw + t + 4];
                unsigned bl0 = Bl[nb * PW + kw + t], bl1 = Bl[nb * PW + kw + t + 4];
                mma16(accE[nt], ah[0], ah[1], ah[2], ah[3], bh0, bh1);
                mma16(accE[nt], ah[0], ah[1], ah[2], ah[3], bl0, bl1);
                mma16(accE[nt], al[0], al[1], al[2], al[3], bh0, bh1);
            }
        }
        #pragma unroll
        for (int nt = 0; nt < 4; nt++) {
            int row = wm * 16 + g;
            int col = chunk * 64 + wn * 32 + nt * 8 + t * 2;
            Gs[row * 132 + col]           = accE[nt][0];
            Gs[row * 132 + col + 1]       = accE[nt][1];
            Gs[(row + 8) * 132 + col]     = accE[nt][2];
            Gs[(row + 8) * 132 + col + 1] = accE[nt][3];
        }
    }
    __syncthreads();

    #pragma unroll
    for (int nt = 0; nt < 4; nt++) {
        int qb = wm * 16 + g;
        int kb = wn * 32 + nt * 8 + t * 2;
        #pragma unroll
        for (int r4 = 0; r4 < 4; r4++) {
            int q = qb + ((r4 >= 2) ? 8 : 0);
            int k = kb + (r4 & 1);
            int c = k + 63 - q;
            float s = (accK[nt][r4] + Gs[q * 132 + c]
                       + gUK[bh * NT + k0 + k] + gVE[h * NR + rbase + c]) * 0.125f;
            gS[(size_t)(bh * NT + q0 + q) * NT + k0 + k] = s;
        }
    }
}

// ---------------- warp-per-row softmax over 1024 columns -----------------
__global__ void softmax_kernel() {
    int row = blockIdx.x * 8 + (threadIdx.x >> 5);
    int lane = threadIdx.x & 31;
    float* p = gS + (size_t)row * NT;
    float4 v[8];
    float m = -1e30f;
    #pragma unroll
    for (int i = 0; i < 8; i++) {
        v[i] = *(float4*)(p + (i * 32 + lane) * 4);
        m = fmaxf(m, fmaxf(fmaxf(v[i].x, v[i].y), fmaxf(v[i].z, v[i].w)));
    }
    #pragma unroll
    for (int o = 16; o; o >>= 1) m = fmaxf(m, __shfl_xor_sync(0xffffffffu, m, o));
    float sum = 0.f;
    #pragma unroll
    for (int i = 0; i < 8; i++) {
        v[i].x = __expf(v[i].x - m); v[i].y = __expf(v[i].y - m);
        v[i].z = __expf(v[i].z - m); v[i].w = __expf(v[i].w - m);
        sum += v[i].x + v[i].y + v[i].z + v[i].w;
    }
    #pragma unroll
    for (int o = 16; o; o >>= 1) sum += __shfl_xor_sync(0xffffffffu, sum, o);
    float inv = 1.f / sum;
    #pragma unroll
    for (int i = 0; i < 8; i++) {
        v[i].x *= inv; v[i].y *= inv; v[i].z *= inv; v[i].w *= inv;
        *(float4*)(p + (i * 32 + lane) * 4) = v[i];
    }
}

// ---------------- O = P @ V (tensor, 3xBF16) -----------------------------
// Block: 256 thr, output 128(q) x 64(d) per (bh, q-tile). k = 1024, chunk 64.
__global__ void pv_tc() {
    extern __shared__ unsigned sm[];
    unsigned* Ph  = sm;                   // 128*PW  (P, k packed in pos-pairs)
    unsigned* Pl  = Ph + 128 * PW;
    unsigned* Vth = Pl + 128 * PW;        // 64*PW, [d][posword]
    unsigned* Vtl = Vth + 64 * PW;
    int tid = threadIdx.x;
    int warp = tid >> 5, lane = tid & 31;
    int wm = warp >> 1, wn = warp & 1;
    int g = lane >> 2, t = lane & 3;
    int bh = blockIdx.y, b = bh >> 3, h = bh & 7;
    int q0 = blockIdx.x * 128;
    float acc[2][4][4] = {};

    for (int kk0 = 0; kk0 < NT; kk0 += 64) {
        #pragma unroll
        for (int i = 0; i < 8; i++) {
            int idx = tid + i * 256;
            int row = idx >> 4, c4 = (idx & 15) << 2;
            float4 pv = *(const float4*)&gS[(size_t)(bh * NT + q0 + row) * NT + kk0 + c4];
            int w = c4 >> 1;
            cvt_pair2(pv.x, pv.y, Ph[row * PW + w],     Pl[row * PW + w]);
            cvt_pair2(pv.z, pv.w, Ph[row * PW + w + 1], Pl[row * PW + w + 1]);
        }
        #pragma unroll
        for (int i = 0; i < 2; i++) {
            int u = tid + i * 256;
            int p = u >> 4, dg = (u & 15) << 2;   // pos pair p (0..31), d group
            const float* v0 = &gV[(size_t)(b * NT + kk0 + 2 * p) * ND + h * NDH + dg];
            const float* v1 = v0 + ND;
            float4 a = *(const float4*)v0;
            float4 c = *(const float4*)v1;
            cvt_pair2(a.x, c.x, Vth[(dg + 0) * PW + p], Vtl[(dg + 0) * PW + p]);
            cvt_pair2(a.y, c.y, Vth[(dg + 1) * PW + p], Vtl[(dg + 1) * PW + p]);
            cvt_pair2(a.z, c.z, Vth[(dg + 2) * PW + p], Vtl[(dg + 2) * PW + p]);
            cvt_pair2(a.w, c.w, Vth[(dg + 3) * PW + p], Vtl[(dg + 3) * PW + p]);
        }
        __syncthreads();
        #pragma unroll
        for (int kw = 0; kw < 32; kw += 8) {
            unsigned ah[2][4], al[2][4];
            #pragma unroll
            for (int mt = 0; mt < 2; mt++) {
                int arow = wm * 32 + mt * 16 + g;
                ah[mt][0] = Ph[arow * PW + kw + t];
                ah[mt][1] = Ph[(arow + 8) * PW + kw + t];
                ah[mt][2] = Ph[arow * PW + kw + t + 4];
                ah[mt][3] = Ph[(arow + 8) * PW + kw + t + 4];
                al[mt][0] = Pl[arow * PW + kw + t];
                al[mt][1] = Pl[(arow + 8) * PW + kw + t];
                al[mt][2] = Pl[arow * PW + kw + t + 4];
                al[mt][3] = Pl[(arow + 8) * PW + kw + t + 4];
            }
            #pragma unroll
            for (int nt = 0; nt < 4; nt++) {
                int nb = wn * 32 + nt * 8 + g;
                unsigned bh0 = Vth[nb * PW + kw + t], bh1 = Vth[nb * PW + kw + t + 4];
                unsigned bl0 = Vtl[nb * PW + kw + t], bl1 = Vtl[nb * PW + kw + t + 4];
                #pragma unroll
                for (int mt = 0; mt < 2; mt++) {
                    mma16(acc[mt][nt], ah[mt][0], ah[mt][1], ah[mt][2], ah[mt][3], bh0, bh1);
                    mma16(acc[mt][nt], ah[mt][0], ah[mt][1], ah[mt][2], ah[mt][3], bl0, bl1);
                    mma16(acc[mt][nt], al[mt][0], al[mt][1], al[mt][2], al[mt][3], bh0, bh1);
                }
            }
        }
        __syncthreads();
    }
    #pragma unroll
    for (int mt = 0; mt < 2; mt++) {
        #pragma unroll
        for (int nt = 0; nt < 4; nt++) {
            int row = q0 + wm * 32 + mt * 16 + g;
            int col = wn * 32 + nt * 8 + t * 2;
            gO[(size_t)(b * NT + row) * ND + h * NDH + col]           = acc[mt][nt][0];
            gO[(size_t)(b * NT + row) * ND + h * NDH + col + 1]       = acc[mt][nt][1];
            gO[(size_t)(b * NT + row + 8) * ND + h * NDH + col]       = acc[mt][nt][2];
            gO[(size_t)(b * NT + row + 8) * ND + h * NDH + col + 1]   = acc[mt][nt][3];
        }
    }
}

// -------------------------------------------------------------------------
extern "C" void kernel_launch(void* const* d_in, const int* in_sizes, int n_in,
                              void* d_out, int out_size) {
    const float* query = (const float*)d_in[0];
    const float* key_  = (const float*)d_in[1];
    const float* value = (const float*)d_in[2];
    const float* Wq = (const float*)d_in[3];
    const float* bq = (const float*)d_in[4];
    const float* Wk = (const float*)d_in[5];
    const float* bk = (const float*)d_in[6];
    const float* Wv = (const float*)d_in[7];
    const float* bv = (const float*)d_in[8];
    const float* Wp = (const float*)d_in[9];
    const float* bp = (const float*)d_in[10];
    const float* Wo = (const float*)d_in[11];
    const float* bo = (const float*)d_in[12];
    const float* ub = (const float*)d_in[13];
    const float* vb = (const float*)d_in[14];
    float* out = (float*)d_out;

    float *pQ, *pK, *pV, *pPE, *pE, *pO;
    cudaGetSymbolAddress((void**)&pQ, gQ);
    cudaGetSymbolAddress((void**)&pK, gK);
    cudaGetSymbolAddress((void**)&pV, gV);
    cudaGetSymbolAddress((void**)&pPE, gPE);
    cudaGetSymbolAddress((void**)&pE, gE);
    cudaGetSymbolAddress((void**)&pO, gO);

    const int PROJ_SMEM   = (2 * 128 * PW + 2 * 64 * PW) * 4;   // 55296
    const int SCORES_SMEM = (4 * 64 * PW) * 4 + (64 * 132) * 4; // 70656
    const int PV_SMEM     = (2 * 128 * PW + 2 * 64 * PW) * 4;   // 55296
    cudaFuncSetAttribute(proj_tc,   cudaFuncAttributeMaxDynamicSharedMemorySize, PROJ_SMEM);
    cudaFuncSetAttribute(scores_tc, cudaFuncAttributeMaxDynamicSharedMemorySize, SCORES_SMEM);
    cudaFuncSetAttribute(pv_tc,     cudaFuncAttributeMaxDynamicSharedMemorySize, PV_SMEM);

    pe_kernel<<<NR, 256>>>();
    proj_tc<<<dim3(8, 32), 256, PROJ_SMEM>>>(query, Wq, bq, pQ, NM);
    proj_tc<<<dim3(8, 32), 256, PROJ_SMEM>>>(key_,  Wk, bk, pK, NM);
    proj_tc<<<dim3(8, 32), 256, PROJ_SMEM>>>(value, Wv, bv, pV, NM);
    proj_tc<<<dim3(8, 16), 256, PROJ_SMEM>>>(pPE,   Wp, bp, pE, NR);
    uk_kernel<<<(NB * NH * NT * 32) / 256, 256>>>(ub);
    ve_kernel<<<(NH * NR * 32 + 255) / 256, 256>>>(vb);
    scores_tc<<<dim3(16, 16, 32), 256, SCORES_SMEM>>>();
    softmax_kernel<<<NB * NH * NT / 8, 256>>>();
    pv_tc<<<dim3(8, 32), 256, PV_SMEM>>>();
    proj_tc<<<dim3(8, 32), 256, PROJ_SMEM>>>(pO, Wo, bo, out, NM);
}

// round 6
// speedup vs baseline: 1.6248x; 1.0321x over previous
#include <cuda_runtime.h>
#include <cuda_bf16.h>
#include <math.h>

// Problem shapes (fixed by the dataset)
#define NB 4
#define NT 1024
#define ND 512
#define NH 8
#define NDH 64
#define NR 2047          // 2*T - 1
#define NM 4096          // B*T
#define NROWS (NB * NH * NT)   // 32768 score rows
#define NKT 16                 // k-tiles per row

#define PW 36            // padded word-row length (32 data words + 4)

// ---------------- device scratch (no allocations allowed) ----------------
__device__ float gQ[NM * ND];
__device__ float gK[NM * ND];
__device__ float gV[NM * ND];
__device__ float gPE[NR * ND];
__device__ float gE[NR * ND];
__device__ float gS[33554432];        // B*H*T*T, holds exp(s - m_tile)
__device__ float gO[NM * ND];
__device__ float gUK[NB * NH * NT];
__device__ float gVE[NH * NR];
__device__ float gPartM[NROWS * NKT]; // per-(row, ktile) max
__device__ float gPartL[NROWS * NKT]; // per-(row, ktile) sum of exp(s - m_tile)
__device__ float gScale[NROWS * NKT]; // exp(m_tile - m_row) / l_row

// ---------------- bf16 split helpers ----------------
__device__ __forceinline__ void cvt_pair2(float a, float b, unsigned& hi, unsigned& lo) {
    unsigned ha = __bfloat16_as_ushort(__float2bfloat16(a));
    unsigned hb = __bfloat16_as_ushort(__float2bfloat16(b));
    float ra = a - __bfloat162float(__ushort_as_bfloat16((unsigned short)ha));
    float rb = b - __bfloat162float(__ushort_as_bfloat16((unsigned short)hb));
    unsigned la = __bfloat16_as_ushort(__float2bfloat16(ra));
    unsigned lb = __bfloat16_as_ushort(__float2bfloat16(rb));
    hi = (hb << 16) | ha;
    lo = (lb << 16) | la;
}
__device__ __forceinline__ void mma16(float (&c)[4], unsigned a0, unsigned a1,
                                      unsigned a2, unsigned a3, unsigned b0, unsigned b1) {
    asm volatile(
        "mma.sync.aligned.m16n8k16.row.col.f32.bf16.bf16.f32 "
        "{%0,%1,%2,%3},{%4,%5,%6,%7},{%8,%9},{%0,%1,%2,%3};"
        : "+f"(c[0]), "+f"(c[1]), "+f"(c[2]), "+f"(c[3])
        : "r"(a0), "r"(a1), "r"(a2), "r"(a3), "r"(b0), "r"(b1));
}

// ---------------- positional encoding (fp32 angle, accurate sin) ----------
__global__ void pe_kernel() {
    int idx = blockIdx.x * 256 + threadIdx.x;
    if (idx >= NR * 256) return;
    int r = idx >> 8;
    int m = idx & 255;
    // inv_freq = 10000^(-2m/512) = 2^(-m * log2(10000)/256)
    float inv = exp2f(-(float)m * (13.287712379549449f / 256.0f));
    float ang = (float)(1023 - r) * inv;        // fp32 product (matches ref)
    gPE[r * ND + 2 * m]     = (float)sin((double)ang);
    gPE[r * ND + 2 * m + 1] = (float)cos((double)ang);
}

// ---------------- GEMM body (shared by proj_all / proj_tc) ---------------
struct ProjArgs {
    const float* A[4];
    const float* W[4];
    const float* bias[4];
    float*       C[4];
    int          M[4];
};

__device__ __forceinline__ void proj_body(const float* __restrict__ A,
                                          const float* __restrict__ W,
                                          const float* __restrict__ bias,
                                          float* __restrict__ C, int M,
                                          int bx, int by, unsigned* sm) {
    unsigned* Ah = sm;                    // 128*PW
    unsigned* Al = Ah + 128 * PW;
    unsigned* Wh = Al + 128 * PW;         // 64*PW, stored [n][kword]
    unsigned* Wl = Wh + 64 * PW;
    int tid = threadIdx.x;
    int warp = tid >> 5, lane = tid & 31;
    int wm = warp >> 1, wn = warp & 1;
    int g = lane >> 2, t = lane & 3;
    int bm = by * 128, bn = bx * 64;
    float acc[2][4][4] = {};

    for (int k0 = 0; k0 < 512; k0 += 64) {
        #pragma unroll
        for (int i = 0; i < 8; i++) {
            int idx = tid + i * 256;
            int row = idx >> 4, c4 = (idx & 15) << 2;
            int grow = bm + row;
            float4 av = (grow < M) ? *(const float4*)&A[(size_t)grow * 512 + k0 + c4]
                                   : make_float4(0.f, 0.f, 0.f, 0.f);
            int w = c4 >> 1;
            cvt_pair2(av.x, av.y, Ah[row * PW + w],     Al[row * PW + w]);
            cvt_pair2(av.z, av.w, Ah[row * PW + w + 1], Al[row * PW + w + 1]);
        }
        #pragma unroll
        for (int i = 0; i < 4; i++) {
            int idx = tid + i * 256;
            int row = idx >> 4, c4 = (idx & 15) << 2;
            float4 wv = *(const float4*)&W[(size_t)(bn + row) * 512 + k0 + c4];
            int w = c4 >> 1;
            cvt_pair2(wv.x, wv.y, Wh[row * PW + w],     Wl[row * PW + w]);
            cvt_pair2(wv.z, wv.w, Wh[row * PW + w + 1], Wl[row * PW + w + 1]);
        }
        __syncthreads();
        #pragma unroll
        for (int kw = 0; kw < 32; kw += 8) {
            unsigned ah[2][4], al[2][4];
            #pragma unroll
            for (int mt = 0; mt < 2; mt++) {
                int ar = wm * 32 + mt * 16 + g;
                ah[mt][0] = Ah[ar * PW + kw + t];
                ah[mt][1] = Ah[(ar + 8) * PW + kw + t];
                ah[mt][2] = Ah[ar * PW + kw + t + 4];
                ah[mt][3] = Ah[(ar + 8) * PW + kw + t + 4];
                al[mt][0] = Al[ar * PW + kw + t];
                al[mt][1] = Al[(ar + 8) * PW + kw + t];
                al[mt][2] = Al[ar * PW + kw + t + 4];
                al[mt][3] = Al[(ar + 8) * PW + kw + t + 4];
            }
            #pragma unroll
            for (int nt = 0; nt < 4; nt++) {
                int nb = wn * 32 + nt * 8 + g;
                unsigned bh0 = Wh[nb * PW + kw + t], bh1 = Wh[nb * PW + kw + t + 4];
                unsigned bl0 = Wl[nb * PW + kw + t], bl1 = Wl[nb * PW + kw + t + 4];
                #pragma unroll
                for (int mt = 0; mt < 2; mt++) {
                    mma16(acc[mt][nt], ah[mt][0], ah[mt][1], ah[mt][2], ah[mt][3], bh0, bh1);
                    mma16(acc[mt][nt], ah[mt][0], ah[mt][1], ah[mt][2], ah[mt][3], bl0, bl1);
                    mma16(acc[mt][nt], al[mt][0], al[mt][1], al[mt][2], al[mt][3], bh0, bh1);
                }
            }
        }
        __syncthreads();
    }
    #pragma unroll
    for (int mt = 0; mt < 2; mt++) {
        #pragma unroll
        for (int nt = 0; nt < 4; nt++) {
            int row = bm + wm * 32 + mt * 16 + g;
            int col = bn + wn * 32 + nt * 8 + t * 2;
            if (row < M) {
                C[(size_t)row * 512 + col]     = acc[mt][nt][0] + bias[col];
                C[(size_t)row * 512 + col + 1] = acc[mt][nt][1] + bias[col + 1];
            }
            if (row + 8 < M) {
                C[(size_t)(row + 8) * 512 + col]     = acc[mt][nt][2] + bias[col];
                C[(size_t)(row + 8) * 512 + col + 1] = acc[mt][nt][3] + bias[col + 1];
            }
        }
    }
}

// all 4 input projections in one launch: blocks [0,768) -> z=0..2 (M=4096, 32 y),
// [768, 896) -> z=3 (E, M=2047, 16 y)
__global__ void proj_all(ProjArgs a) {
    extern __shared__ unsigned sm[];
    int bid = blockIdx.x;
    int z, bx, by;
    if (bid < 768) { z = bid >> 8; int r = bid & 255; by = r >> 3; bx = r & 7; }
    else           { z = 3;        int r = bid - 768; by = r >> 3; bx = r & 7; }
    proj_body(a.A[z], a.W[z], a.bias[z], a.C[z], a.M[z], bx, by, sm);
}

__global__ void proj_tc(const float* __restrict__ A, const float* __restrict__ W,
                        const float* __restrict__ bias, float* __restrict__ C, int M) {
    extern __shared__ unsigned sm[];
    proj_body(A, W, bias, C, M, blockIdx.x, blockIdx.y, sm);
}

// ---------------- gUK + gVE fused -------------------------------------
__global__ void ukve_kernel(const float* __restrict__ u, const float* __restrict__ v) {
    int gid = blockIdx.x * 256 + threadIdx.x;
    int w = gid >> 5, lane = gid & 31;
    if (w < NB * NH * NT) {
        int t = w & (NT - 1);
        int bh = w >> 10;
        int h = bh & 7, b = bh >> 3;
        const float* kp = gK + (size_t)(b * NT + t) * ND + h * NDH;
        const float* up = u + h * NDH;
        float s = kp[lane] * up[lane] + kp[lane + 32] * up[lane + 32];
        #pragma unroll
        for (int o = 16; o; o >>= 1) s += __shfl_down_sync(0xffffffffu, s, o);
        if (lane == 0) gUK[bh * NT + t] = s;
    } else {
        int w2 = w - NB * NH * NT;
        if (w2 >= NH * NR) return;
        int h = w2 / NR;
        int r = w2 - h * NR;
        const float* ep = gE + (size_t)r * ND + h * NDH;
        const float* vp = v + h * NDH;
        float s = ep[lane] * vp[lane] + ep[lane + 32] * vp[lane + 32];
        #pragma unroll
        for (int o = 16; o; o >>= 1) s += __shfl_down_sync(0xffffffffu, s, o);
        if (lane == 0) gVE[h * NR + r] = s;
    }
}

// ---------------- scores (3xBF16) + per-tile softmax stats ----------------
// Writes exp(s - m_tile) to gS and (m_tile, sum_tile) per row to gPartM/L.
__global__ void scores_tc() {
    extern __shared__ unsigned sm[];
    unsigned* Qh = sm;                    // 64*PW
    unsigned* Ql = Qh + 64 * PW;
    unsigned* Bh = Ql + 64 * PW;          // K tile then E chunks, [n][dword]
    unsigned* Bl = Bh + 64 * PW;
    float* Gs   = (float*)(Bl + 64 * PW); // 64*132
    float* redM = Gs + 64 * 132;          // [2][64]
    float* redL = redM + 128;             // [2][64]
    int tid = threadIdx.x;
    int bh = blockIdx.z, h = bh & 7, b = bh >> 3;
    int q0 = blockIdx.y * 64, k0 = blockIdx.x * 64;
    int warp = tid >> 5, lane = tid & 31;
    int wm = warp >> 1, wn = warp & 1;
    int g = lane >> 2, t = lane & 3;

    #pragma unroll
    for (int i = 0; i < 4; i++) {
        int idx = tid + i * 256;
        int row = idx >> 4, c4 = (idx & 15) << 2;
        float4 qv = *(const float4*)&gQ[(size_t)(b * NT + q0 + row) * ND + h * NDH + c4];
        float4 kv = *(const float4*)&gK[(size_t)(b * NT + k0 + row) * ND + h * NDH + c4];
        int w = c4 >> 1;
        cvt_pair2(qv.x, qv.y, Qh[row * PW + w],     Ql[row * PW + w]);
        cvt_pair2(qv.z, qv.w, Qh[row * PW + w + 1], Ql[row * PW + w + 1]);
        cvt_pair2(kv.x, kv.y, Bh[row * PW + w],     Bl[row * PW + w]);
        cvt_pair2(kv.z, kv.w, Bh[row * PW + w + 1], Bl[row * PW + w + 1]);
    }
    __syncthreads();

    float accK[4][4] = {};
    int ar = wm * 16 + g;
    #pragma unroll
    for (int kw = 0; kw < 32; kw += 8) {
        unsigned ah[4], al[4];
        ah[0] = Qh[ar * PW + kw + t];       ah[1] = Qh[(ar + 8) * PW + kw + t];
        ah[2] = Qh[ar * PW + kw + t + 4];   ah[3] = Qh[(ar + 8) * PW + kw + t + 4];
        al[0] = Ql[ar * PW + kw + t];       al[1] = Ql[(ar + 8) * PW + kw + t];
        al[2] = Ql[ar * PW + kw + t + 4];   al[3] = Ql[(ar + 8) * PW + kw + t + 4];
        #pragma unroll
        for (int nt = 0; nt < 4; nt++) {
            int nb = wn * 32 + nt * 8 + g;
            unsigned bh0 = Bh[nb * PW + kw + t], bh1 = Bh[nb * PW + kw + t + 4];
            unsigned bl0 = Bl[nb * PW + kw + t], bl1 = Bl[nb * PW + kw + t + 4];
            mma16(accK[nt], ah[0], ah[1], ah[2], ah[3], bh0, bh1);
            mma16(accK[nt], ah[0], ah[1], ah[2], ah[3], bl0, bl1);
            mma16(accK[nt], al[0], al[1], al[2], al[3], bh0, bh1);
        }
    }

    int rbase = 960 + k0 - q0;   // >= 0 always
    for (int chunk = 0; chunk < 2; chunk++) {
        __syncthreads();
        #pragma unroll
        for (int i = 0; i < 4; i++) {
            int idx = tid + i * 256;
            int row = idx >> 4, c4 = (idx & 15) << 2;
            int r = rbase + chunk * 64 + row;
            float4 ev = (r < NR) ? *(const float4*)&gE[(size_t)r * ND + h * NDH + c4]
                                 : make_float4(0.f, 0.f, 0.f, 0.f);
            int w = c4 >> 1;
            cvt_pair2(ev.x, ev.y, Bh[row * PW + w],     Bl[row * PW + w]);
            cvt_pair2(ev.z, ev.w, Bh[row * PW + w + 1], Bl[row * PW + w + 1]);
        }
        __syncthreads();
        float accE[4][4] = {};
        #pragma unroll
        for (int kw = 0; kw < 32; kw += 8) {
            unsigned ah[4], al[4];
            ah[0] = Qh[ar * PW + kw + t];       ah[1] = Qh[(ar + 8) * PW + kw + t];
            ah[2] = Qh[ar * PW + kw + t + 4];   ah[3] = Qh[(ar + 8) * PW + kw + t + 4];
            al[0] = Ql[ar * PW + kw + t];       al[1] = Ql[(ar + 8) * PW + kw + t];
            al[2] = Ql[ar * PW + kw + t + 4];   al[3] = Ql[(ar + 8) * PW + kw + t + 4];
            #pragma unroll
            for (int nt = 0; nt < 4; nt++) {
                int nb = wn * 32 + nt * 8 + g;
                unsigned bh0 = Bh[nb * PW + kw + t], bh1 = Bh[nb * PW + kw + t + 4];
                unsigned bl0 = Bl[nb * PW + kw + t], bl1 = Bl[nb * PW + kw + t + 4];
                mma16(accE[nt], ah[0], ah[1], ah[2], ah[3], bh0, bh1);
                mma16(accE[nt], ah[0], ah[1], ah[2], ah[3], bl0, bl1);
                mma16(accE[nt], al[0], al[1], al[2], al[3], bh0, bh1);
            }
        }
        #pragma unroll
        for (int nt = 0; nt < 4; nt++) {
            int col = chunk * 64 + wn * 32 + nt * 8 + t * 2;
            Gs[ar * 132 + col]           = accE[nt][0];
            Gs[ar * 132 + col + 1]       = accE[nt][1];
            Gs[(ar + 8) * 132 + col]     = accE[nt][2];
            Gs[(ar + 8) * 132 + col + 1] = accE[nt][3];
        }
    }
    __syncthreads();

    // ---- full raw scores in registers ----
    #pragma unroll
    for (int nt = 0; nt < 4; nt++) {
        int kb = wn * 32 + nt * 8 + t * 2;
        #pragma unroll
        for (int r4 = 0; r4 < 4; r4++) {
            int q = ar + ((r4 >= 2) ? 8 : 0);
            int k = kb + (r4 & 1);
            int c = k + 63 - q;
            accK[nt][r4] = (accK[nt][r4] + Gs[q * 132 + c]
                            + gUK[bh * NT + k0 + k] + gVE[h * NR + rbase + c]) * 0.125f;
        }
    }

    // ---- per-tile row max ----
    float m0 = -1e30f, m1 = -1e30f;
    #pragma unroll
    for (int nt = 0; nt < 4; nt++) {
        m0 = fmaxf(m0, fmaxf(accK[nt][0], accK[nt][1]));
        m1 = fmaxf(m1, fmaxf(accK[nt][2], accK[nt][3]));
    }
    m0 = fmaxf(m0, __shfl_xor_sync(0xffffffffu, m0, 1));
    m0 = fmaxf(m0, __shfl_xor_sync(0xffffffffu, m0, 2));
    m1 = fmaxf(m1, __shfl_xor_sync(0xffffffffu, m1, 1));
    m1 = fmaxf(m1, __shfl_xor_sync(0xffffffffu, m1, 2));
    if (t == 0) {
        redM[wn * 64 + ar]     = m0;
        redM[wn * 64 + ar + 8] = m1;
    }
    __syncthreads();
    m0 = fmaxf(redM[ar],     redM[64 + ar]);
    m1 = fmaxf(redM[ar + 8], redM[64 + ar + 8]);

    // ---- exp + row sums ----
    float sum0 = 0.f, sum1 = 0.f;
    #pragma unroll
    for (int nt = 0; nt < 4; nt++) {
        accK[nt][0] = __expf(accK[nt][0] - m0);
        accK[nt][1] = __expf(accK[nt][1] - m0);
        accK[nt][2] = __expf(accK[nt][2] - m1);
        accK[nt][3] = __expf(accK[nt][3] - m1);
        sum0 += accK[nt][0] + accK[nt][1];
        sum1 += accK[nt][2] + accK[nt][3];
    }
    sum0 += __shfl_xor_sync(0xffffffffu, sum0, 1);
    sum0 += __shfl_xor_sync(0xffffffffu, sum0, 2);
    sum1 += __shfl_xor_sync(0xffffffffu, sum1, 1);
    sum1 += __shfl_xor_sync(0xffffffffu, sum1, 2);
    if (t == 0) {
        redL[wn * 64 + ar]     = sum0;
        redL[wn * 64 + ar + 8] = sum1;
    }
    __syncthreads();
    if (wn == 0 && t == 0) {
        size_t r0 = (size_t)(bh * NT + q0 + ar) * NKT + blockIdx.x;
        size_t r1 = (size_t)(bh * NT + q0 + ar + 8) * NKT + blockIdx.x;
        gPartM[r0] = m0;  gPartL[r0] = redL[ar]     + redL[64 + ar];
        gPartM[r1] = m1;  gPartL[r1] = redL[ar + 8] + redL[64 + ar + 8];
    }

    // ---- store exp values ----
    #pragma unroll
    for (int nt = 0; nt < 4; nt++) {
        int kb = wn * 32 + nt * 8 + t * 2;
        #pragma unroll
        for (int r4 = 0; r4 < 4; r4++) {
            int q = ar + ((r4 >= 2) ? 8 : 0);
            int k = kb + (r4 & 1);
            gS[(size_t)(bh * NT + q0 + q) * NT + k0 + k] = accK[nt][r4];
        }
    }
}

// ---------------- combine per-tile stats -> per-(row,tile) scales --------
__global__ void reduce_kernel() {
    int row = blockIdx.x * 256 + threadIdx.x;
    if (row >= NROWS) return;
    size_t base = (size_t)row * NKT;
    float m = -1e30f;
    float pm[NKT], pl[NKT];
    #pragma unroll
    for (int i = 0; i < NKT; i++) {
        pm[i] = gPartM[base + i];
        pl[i] = gPartL[base + i];
        m = fmaxf(m, pm[i]);
    }
    float l = 0.f;
    #pragma unroll
    for (int i = 0; i < NKT; i++) l += __expf(pm[i] - m) * pl[i];
    float inv = 1.f / l;
    #pragma unroll
    for (int i = 0; i < NKT; i++) gScale[base + i] = __expf(pm[i] - m) * inv;
}

// ---------------- O = P @ V (3xBF16), P scaled on load -------------------
// 64(q) x 64(d) tile, grid (16, 32), k = 1024 in chunks of 64.
__global__ void pv_tc() {
    extern __shared__ unsigned sm[];
    unsigned* Ph  = sm;                   // 64*PW
    unsigned* Pl  = Ph + 64 * PW;
    unsigned* Vth = Pl + 64 * PW;         // 64*PW, [d][posword]
    unsigned* Vtl = Vth + 64 * PW;
    int tid = threadIdx.x;
    int warp = tid >> 5, lane = tid & 31;
    int wm = warp >> 1, wn = warp & 1;
    int g = lane >> 2, t = lane & 3;
    int bh = blockIdx.y, b = bh >> 3, h = bh & 7;
    int q0 = blockIdx.x * 64;
    float acc[4][4] = {};
    int ar = wm * 16 + g;

    for (int kk0 = 0; kk0 < NT; kk0 += 64) {
        int ktile = kk0 >> 6;
        #pragma unroll
        for (int i = 0; i < 4; i++) {
            int idx = tid + i * 256;
            int row = idx >> 4, c4 = (idx & 15) << 2;
            float sc = gScale[(size_t)(bh * NT + q0 + row) * NKT + ktile];
            float4 pv = *(const float4*)&gS[(size_t)(bh * NT + q0 + row) * NT + kk0 + c4];
            int w = c4 >> 1;
            cvt_pair2(pv.x * sc, pv.y * sc, Ph[row * PW + w],     Pl[row * PW + w]);
            cvt_pair2(pv.z * sc, pv.w * sc, Ph[row * PW + w + 1], Pl[row * PW + w + 1]);
        }
        #pragma unroll
        for (int i = 0; i < 2; i++) {
            int u = tid + i * 256;
            int p = u >> 4, dg = (u & 15) << 2;   // pos pair p (0..31), d group
            const float* v0 = &gV[(size_t)(b * NT + kk0 + 2 * p) * ND + h * NDH + dg];
            const float* v1 = v0 + ND;
            float4 a = *(const float4*)v0;
            float4 c = *(const float4*)v1;
            cvt_pair2(a.x, c.x, Vth[(dg + 0) * PW + p], Vtl[(dg + 0) * PW + p]);
            cvt_pair2(a.y, c.y, Vth[(dg + 1) * PW + p], Vtl[(dg + 1) * PW + p]);
            cvt_pair2(a.z, c.z, Vth[(dg + 2) * PW + p], Vtl[(dg + 2) * PW + p]);
            cvt_pair2(a.w, c.w, Vth[(dg + 3) * PW + p], Vtl[(dg + 3) * PW + p]);
        }
        __syncthreads();
        #pragma unroll
        for (int kw = 0; kw < 32; kw += 8) {
            unsigned ah[4], al[4];
            ah[0] = Ph[ar * PW + kw + t];       ah[1] = Ph[(ar + 8) * PW + kw + t];
            ah[2] = Ph[ar * PW + kw + t + 4];   ah[3] = Ph[(ar + 8) * PW + kw + t + 4];
            al[0] = Pl[ar * PW + kw + t];       al[1] = Pl[(ar + 8) * PW + kw + t];
            al[2] = Pl[ar * PW + kw + t + 4];   al[3] = Pl[(ar + 8) * PW + kw + t + 4];
            #pragma unroll
            for (int nt = 0; nt < 4; nt++) {
                int nb = wn * 32 + nt * 8 + g;
                unsigned bh0 = Vth[nb * PW + kw + t], bh1 = Vth[nb * PW + kw + t + 4];
                unsigned bl0 = Vtl[nb * PW + kw + t], bl1 = Vtl[nb * PW + kw + t + 4];
                mma16(acc[nt], ah[0], ah[1], ah[2], ah[3], bh0, bh1);
                mma16(acc[nt], ah[0], ah[1], ah[2], ah[3], bl0, bl1);
                mma16(acc[nt], al[0], al[1], al[2], al[3], bh0, bh1);
            }
        }
        __syncthreads();
    }
    #pragma unroll
    for (int nt = 0; nt < 4; nt++) {
        int row = q0 + ar;
        int col = wn * 32 + nt * 8 + t * 2;
        gO[(size_t)(b * NT + row) * ND + h * NDH + col]         = acc[nt][0];
        gO[(size_t)(b * NT + row) * ND + h * NDH + col + 1]     = acc[nt][1];
        gO[(size_t)(b * NT + row + 8) * ND + h * NDH + col]     = acc[nt][2];
        gO[(size_t)(b * NT + row + 8) * ND + h * NDH + col + 1] = acc[nt][3];
    }
}

// -------------------------------------------------------------------------
extern "C" void kernel_launch(void* const* d_in, const int* in_sizes, int n_in,
                              void* d_out, int out_size) {
    const float* query = (const float*)d_in[0];
    const float* key_  = (const float*)d_in[1];
    const float* value = (const float*)d_in[2];
    const float* Wq = (const float*)d_in[3];
    const float* bq = (const float*)d_in[4];
    const float* Wk = (const float*)d_in[5];
    const float* bk = (const float*)d_in[6];
    const float* Wv = (const float*)d_in[7];
    const float* bv = (const float*)d_in[8];
    const float* Wp = (const float*)d_in[9];
    const float* bp = (const float*)d_in[10];
    const float* Wo = (const float*)d_in[11];
    const float* bo = (const float*)d_in[12];
    const float* ub = (const float*)d_in[13];
    const float* vb = (const float*)d_in[14];
    float* out = (float*)d_out;

    float *pQ, *pK, *pV, *pPE, *pE, *pO;
    cudaGetSymbolAddress((void**)&pQ, gQ);
    cudaGetSymbolAddress((void**)&pK, gK);
    cudaGetSymbolAddress((void**)&pV, gV);
    cudaGetSymbolAddress((void**)&pPE, gPE);
    cudaGetSymbolAddress((void**)&pE, gE);
    cudaGetSymbolAddress((void**)&pO, gO);

    const int PROJ_SMEM   = (2 * 128 * PW + 2 * 64 * PW) * 4;                // 55296
    const int SCORES_SMEM = (4 * 64 * PW) * 4 + (64 * 132) * 4 + 256 * 4;    // 71680
    const int PV_SMEM     = (4 * 64 * PW) * 4;                               // 36864
    cudaFuncSetAttribute(proj_all,  cudaFuncAttributeMaxDynamicSharedMemorySize, PROJ_SMEM);
    cudaFuncSetAttribute(proj_tc,   cudaFuncAttributeMaxDynamicSharedMemorySize, PROJ_SMEM);
    cudaFuncSetAttribute(scores_tc, cudaFuncAttributeMaxDynamicSharedMemorySize, SCORES_SMEM);
    cudaFuncSetAttribute(pv_tc,     cudaFuncAttributeMaxDynamicSharedMemorySize, PV_SMEM);

    ProjArgs pa;
    pa.A[0] = query; pa.W[0] = Wq; pa.bias[0] = bq; pa.C[0] = pQ; pa.M[0] = NM;
    pa.A[1] = key_;  pa.W[1] = Wk; pa.bias[1] = bk; pa.C[1] = pK; pa.M[1] = NM;
    pa.A[2] = value; pa.W[2] = Wv; pa.bias[2] = bv; pa.C[2] = pV; pa.M[2] = NM;
    pa.A[3] = pPE;   pa.W[3] = Wp; pa.bias[3] = bp; pa.C[3] = pE; pa.M[3] = NR;

    pe_kernel<<<NR, 256>>>();
    proj_all<<<896, 256, PROJ_SMEM>>>(pa);
    ukve_kernel<<<6143, 256>>>(ub, vb);
    scores_tc<<<dim3(16, 16, 32), 256, SCORES_SMEM>>>();
    reduce_kernel<<<128, 256>>>();
    pv_tc<<<dim3(16, 32), 256, PV_SMEM>>>();
    proj_tc<<<dim3(8, 32), 256, PROJ_SMEM>>>(pO, Wo, bo, out, NM);
}

// round 8
// speedup vs baseline: 1.6314x; 1.0040x over previous
#include <cuda_runtime.h>
#include <cuda_bf16.h>
#include <math.h>

// Problem shapes (fixed by the dataset)
#define NB 4
#define NT 1024
#define ND 512
#define NH 8
#define NDH 64
#define NR 2047          // 2*T - 1
#define NM 4096          // B*T
#define NROWS (NB * NH * NT)   // 32768 score rows
#define NKT 16                 // k-tiles per row

#define PW 36            // padded word-row length (32 data words + 4)

// ---------------- device scratch (no allocations allowed) ----------------
__device__ float gQ[NM * ND];
__device__ float gK[NM * ND];
__device__ float gV[NM * ND];
__device__ float gPE[NR * ND];
__device__ float gE[NR * ND];
__device__ float gS[33554432];        // B*H*T*T, holds exp(s - m_tile)
__device__ float gO[NM * ND];
__device__ float gUK[NB * NH * NT];
__device__ float gVE[NH * NR];
__device__ float gPartM[NROWS * NKT];
__device__ float gPartL[NROWS * NKT];
__device__ float gScale[NROWS * NKT];

// ---------------- bf16 split helpers ----------------
__device__ __forceinline__ void cvt_pair2(float a, float b, unsigned& hi, unsigned& lo) {
    unsigned ha = __bfloat16_as_ushort(__float2bfloat16(a));
    unsigned hb = __bfloat16_as_ushort(__float2bfloat16(b));
    float ra = a - __bfloat162float(__ushort_as_bfloat16((unsigned short)ha));
    float rb = b - __bfloat162float(__ushort_as_bfloat16((unsigned short)hb));
    unsigned la = __bfloat16_as_ushort(__float2bfloat16(ra));
    unsigned lb = __bfloat16_as_ushort(__float2bfloat16(rb));
    hi = (hb << 16) | ha;
    lo = (lb << 16) | la;
}
__device__ __forceinline__ void mma16(float (&c)[4], unsigned a0, unsigned a1,
                                      unsigned a2, unsigned a3, unsigned b0, unsigned b1) {
    asm volatile(
        "mma.sync.aligned.m16n8k16.row.col.f32.bf16.bf16.f32 "
        "{%0,%1,%2,%3},{%4,%5,%6,%7},{%8,%9},{%0,%1,%2,%3};"
        : "+f"(c[0]), "+f"(c[1]), "+f"(c[2]), "+f"(c[3])
        : "r"(a0), "r"(a1), "r"(a2), "r"(a3), "r"(b0), "r"(b1));
}
__device__ __forceinline__ unsigned smaddr(const void* p) {
    return (unsigned)__cvta_generic_to_shared(p);
}
__device__ __forceinline__ void ldsm4(unsigned& r0, unsigned& r1, unsigned& r2,
                                      unsigned& r3, unsigned a) {
    asm volatile("ldmatrix.sync.aligned.m8n8.x4.shared.b16 {%0,%1,%2,%3}, [%4];"
                 : "=r"(r0), "=r"(r1), "=r"(r2), "=r"(r3) : "r"(a));
}
// A-fragment lane offset (bytes): row = lane&15, +16B for lanes 16-31
#define AOFF(lane) (((((lane) & 15) * PW + ((lane) >> 4) * 4)) << 2)
// B-fragment lane offset (two n-blocks of 8)
#define BOFF(lane) (((((((lane) >> 4) << 3) + ((lane) & 7)) * PW + (((lane) >> 3) & 1) * 4)) << 2)

// ---------------- positional encoding ----------------
__global__ void pe_kernel() {
    int idx = blockIdx.x * 256 + threadIdx.x;
    if (idx >= NR * 256) return;
    int r = idx >> 8;
    int m = idx & 255;
    float inv = exp2f(-(float)m * (13.287712379549449f / 256.0f));
    float ang = (float)(1023 - r) * inv;
    gPE[r * ND + 2 * m]     = (float)sin((double)ang);
    gPE[r * ND + 2 * m + 1] = (float)cos((double)ang);
}

// ---------------- GEMM body (shared by proj_all / proj_tc) ---------------
struct ProjArgs {
    const float* A[4];
    const float* W[4];
    const float* bias[4];
    float*       C[4];
    int          M[4];
};

__device__ __forceinline__ void proj_body(const float* __restrict__ A,
                                          const float* __restrict__ W,
                                          const float* __restrict__ bias,
                                          float* __restrict__ C, int M,
                                          int bx, int by, unsigned* sm) {
    unsigned* Ah = sm;                    // 128*PW
    unsigned* Al = Ah + 128 * PW;
    unsigned* Wh = Al + 128 * PW;         // 64*PW, stored [n][kword]
    unsigned* Wl = Wh + 64 * PW;
    int tid = threadIdx.x;
    int warp = tid >> 5, lane = tid & 31;
    int wm = warp >> 1, wn = warp & 1;
    int g = lane >> 2, t = lane & 3;
    int bm = by * 128, bn = bx * 64;
    float acc[2][4][4] = {};
    unsigned uAh = smaddr(Ah), uAl = smaddr(Al), uWh = smaddr(Wh), uWl = smaddr(Wl);
    unsigned aoff = AOFF(lane), boff = BOFF(lane);

    for (int k0 = 0; k0 < 512; k0 += 64) {
        #pragma unroll
        for (int i = 0; i < 8; i++) {
            int idx = tid + i * 256;
            int row = idx >> 4, c4 = (idx & 15) << 2;
            int grow = bm + row;
            float4 av = (grow < M) ? *(const float4*)&A[(size_t)grow * 512 + k0 + c4]
                                   : make_float4(0.f, 0.f, 0.f, 0.f);
            int w = c4 >> 1;
            unsigned h0, l0, h1, l1;
            cvt_pair2(av.x, av.y, h0, l0);
            cvt_pair2(av.z, av.w, h1, l1);
            *(uint2*)&Ah[row * PW + w] = make_uint2(h0, h1);
            *(uint2*)&Al[row * PW + w] = make_uint2(l0, l1);
        }
        #pragma unroll
        for (int i = 0; i < 4; i++) {
            int idx = tid + i * 256;
            int row = idx >> 4, c4 = (idx & 15) << 2;
            float4 wv = *(const float4*)&W[(size_t)(bn + row) * 512 + k0 + c4];
            int w = c4 >> 1;
            unsigned h0, l0, h1, l1;
            cvt_pair2(wv.x, wv.y, h0, l0);
            cvt_pair2(wv.z, wv.w, h1, l1);
            *(uint2*)&Wh[row * PW + w] = make_uint2(h0, h1);
            *(uint2*)&Wl[row * PW + w] = make_uint2(l0, l1);
        }
        __syncthreads();
        #pragma unroll
        for (int kw = 0; kw < 32; kw += 8) {
            unsigned ah[2][4], al[2][4];
            #pragma unroll
            for (int mt = 0; mt < 2; mt++) {
                unsigned base = (((wm * 32 + mt * 16) * PW + kw) << 2) + aoff;
                ldsm4(ah[mt][0], ah[mt][1], ah[mt][2], ah[mt][3], uAh + base);
                ldsm4(al[mt][0], al[mt][1], al[mt][2], al[mt][3], uAl + base);
            }
            #pragma unroll
            for (int pair = 0; pair < 2; pair++) {
                unsigned base = (((wn * 32 + pair * 16) * PW + kw) << 2) + boff;
                unsigned bh[4], bl[4];
                ldsm4(bh[0], bh[1], bh[2], bh[3], uWh + base);
                ldsm4(bl[0], bl[1], bl[2], bl[3], uWl + base);
                #pragma unroll
                for (int half = 0; half < 2; half++) {
                    int nt = pair * 2 + half;
                    unsigned bh0 = bh[half * 2], bh1 = bh[half * 2 + 1];
                    unsigned bl0 = bl[half * 2], bl1 = bl[half * 2 + 1];
                    #pragma unroll
                    for (int mt = 0; mt < 2; mt++) {
                        mma16(acc[mt][nt], ah[mt][0], ah[mt][1], ah[mt][2], ah[mt][3], bh0, bh1);
                        mma16(acc[mt][nt], ah[mt][0], ah[mt][1], ah[mt][2], ah[mt][3], bl0, bl1);
                        mma16(acc[mt][nt], al[mt][0], al[mt][1], al[mt][2], al[mt][3], bh0, bh1);
                    }
                }
            }
        }
        __syncthreads();
    }
    #pragma unroll
    for (int mt = 0; mt < 2; mt++) {
        #pragma unroll
        for (int nt = 0; nt < 4; nt++) {
            int row = bm + wm * 32 + mt * 16 + g;
            int col = bn + wn * 32 + nt * 8 + t * 2;
            if (row < M) {
                C[(size_t)row * 512 + col]     = acc[mt][nt][0] + bias[col];
                C[(size_t)row * 512 + col + 1] = acc[mt][nt][1] + bias[col + 1];
            }
            if (row + 8 < M) {
                C[(size_t)(row + 8) * 512 + col]     = acc[mt][nt][2] + bias[col];
                C[(size_t)(row + 8) * 512 + col + 1] = acc[mt][nt][3] + bias[col + 1];
            }
        }
    }
}

__global__ void proj_all(ProjArgs a) {
    extern __shared__ unsigned sm[];
    int bid = blockIdx.x;
    int z, bx, by;
    if (bid < 768) { z = bid >> 8; int r = bid & 255; by = r >> 3; bx = r & 7; }
    else           { z = 3;        int r = bid - 768; by = r >> 3; bx = r & 7; }
    proj_body(a.A[z], a.W[z], a.bias[z], a.C[z], a.M[z], bx, by, sm);
}

__global__ void proj_tc(const float* __restrict__ A, const float* __restrict__ W,
                        const float* __restrict__ bias, float* __restrict__ C, int M) {
    extern __shared__ unsigned sm[];
    proj_body(A, W, bias, C, M, blockIdx.x, blockIdx.y, sm);
}

// ---------------- gUK + gVE fused -------------------------------------
__global__ void ukve_kernel(const float* __restrict__ u, const float* __restrict__ v) {
    int gid = blockIdx.x * 256 + threadIdx.x;
    int w = gid >> 5, lane = gid & 31;
    if (w < NB * NH * NT) {
        int t = w & (NT - 1);
        int bh = w >> 10;
        int h = bh & 7, b = bh >> 3;
        const float* kp = gK + (size_t)(b * NT + t) * ND + h * NDH;
        const float* up = u + h * NDH;
        float s = kp[lane] * up[lane] + kp[lane + 32] * up[lane + 32];
        #pragma unroll
        for (int o = 16; o; o >>= 1) s += __shfl_down_sync(0xffffffffu, s, o);
        if (lane == 0) gUK[bh * NT + t] = s;
    } else {
        int w2 = w - NB * NH * NT;
        if (w2 >= NH * NR) return;
        int h = w2 / NR;
        int r = w2 - h * NR;
        const float* ep = gE + (size_t)r * ND + h * NDH;
        const float* vp = v + h * NDH;
        float s = ep[lane] * vp[lane] + ep[lane + 32] * vp[lane + 32];
        #pragma unroll
        for (int o = 16; o; o >>= 1) s += __shfl_down_sync(0xffffffffu, s, o);
        if (lane == 0) gVE[h * NR + r] = s;
    }
}

// ---------------- scores (3xBF16 + ldmatrix) + per-tile softmax stats -----
__global__ void scores_tc() {
    extern __shared__ unsigned sm[];
    unsigned* Qh = sm;                    // 64*PW
    unsigned* Ql = Qh + 64 * PW;
    unsigned* Bh = Ql + 64 * PW;          // K tile then E chunks, [n][dword]
    unsigned* Bl = Bh + 64 * PW;
    float* Gs   = (float*)(Bl + 64 * PW); // 64*132
    float* redM = Gs + 64 * 132;          // [2][64]
    float* redL = redM + 128;             // [2][64]
    int tid = threadIdx.x;
    int bh = blockIdx.z, h = bh & 7, b = bh >> 3;
    int q0 = blockIdx.y * 64, k0 = blockIdx.x * 64;
    int warp = tid >> 5, lane = tid & 31;
    int wm = warp >> 1, wn = warp & 1;
    int g = lane >> 2, t = lane & 3;
    unsigned uQh = smaddr(Qh), uQl = smaddr(Ql), uBh = smaddr(Bh), uBl = smaddr(Bl);
    unsigned aoff = AOFF(lane), boff = BOFF(lane);
    unsigned abase = ((wm * 16 * PW) << 2) + aoff;

    #pragma unroll
    for (int i = 0; i < 4; i++) {
        int idx = tid + i * 256;
        int row = idx >> 4, c4 = (idx & 15) << 2;
        float4 qv = *(const float4*)&gQ[(size_t)(b * NT + q0 + row) * ND + h * NDH + c4];
        float4 kv = *(const float4*)&gK[(size_t)(b * NT + k0 + row) * ND + h * NDH + c4];
        int w = c4 >> 1;
        unsigned h0, l0, h1, l1;
        cvt_pair2(qv.x, qv.y, h0, l0);
        cvt_pair2(qv.z, qv.w, h1, l1);
        *(uint2*)&Qh[row * PW + w] = make_uint2(h0, h1);
        *(uint2*)&Ql[row * PW + w] = make_uint2(l0, l1);
        cvt_pair2(kv.x, kv.y, h0, l0);
        cvt_pair2(kv.z, kv.w, h1, l1);
        *(uint2*)&Bh[row * PW + w] = make_uint2(h0, h1);
        *(uint2*)&Bl[row * PW + w] = make_uint2(l0, l1);
    }
    __syncthreads();

    float accK[4][4] = {};
    int ar = wm * 16 + g;
    #pragma unroll
    for (int kw = 0; kw < 32; kw += 8) {
        unsigned ah[4], al[4];
        ldsm4(ah[0], ah[1], ah[2], ah[3], uQh + abase + (kw << 2));
        ldsm4(al[0], al[1], al[2], al[3], uQl + abase + (kw << 2));
        #pragma unroll
        for (int pair = 0; pair < 2; pair++) {
            unsigned base = (((wn * 32 + pair * 16) * PW + kw) << 2) + boff;
            unsigned bhv[4], blv[4];
            ldsm4(bhv[0], bhv[1], bhv[2], bhv[3], uBh + base);
            ldsm4(blv[0], blv[1], blv[2], blv[3], uBl + base);
            #pragma unroll
            for (int half = 0; half < 2; half++) {
                int nt = pair * 2 + half;
                mma16(accK[nt], ah[0], ah[1], ah[2], ah[3], bhv[half*2], bhv[half*2+1]);
                mma16(accK[nt], ah[0], ah[1], ah[2], ah[3], blv[half*2], blv[half*2+1]);
                mma16(accK[nt], al[0], al[1], al[2], al[3], bhv[half*2], bhv[half*2+1]);
            }
        }
    }

    int rbase = 960 + k0 - q0;   // >= 0 always
    for (int chunk = 0; chunk < 2; chunk++) {
        __syncthreads();
        #pragma unroll
        for (int i = 0; i < 4; i++) {
            int idx = tid + i * 256;
            int row = idx >> 4, c4 = (idx & 15) << 2;
            int r = rbase + chunk * 64 + row;
            float4 ev = (r < NR) ? *(const float4*)&gE[(size_t)r * ND + h * NDH + c4]
                                 : make_float4(0.f, 0.f, 0.f, 0.f);
            int w = c4 >> 1;
            unsigned h0, l0, h1, l1;
            cvt_pair2(ev.x, ev.y, h0, l0);
            cvt_pair2(ev.z, ev.w, h1, l1);
            *(uint2*)&Bh[row * PW + w] = make_uint2(h0, h1);
            *(uint2*)&Bl[row * PW + w] = make_uint2(l0, l1);
        }
        __syncthreads();
        float accE[4][4] = {};
        #pragma unroll
        for (int kw = 0; kw < 32; kw += 8) {
            unsigned ah[4], al[4];
            ldsm4(ah[0], ah[1], ah[2], ah[3], uQh + abase + (kw << 2));
            ldsm4(al[0], al[1], al[2], al[3], uQl + abase + (kw << 2));
            #pragma unroll
            for (int pair = 0; pair < 2; pair++) {
                unsigned base = (((wn * 32 + pair * 16) * PW + kw) << 2) + boff;
                unsigned bhv[4], blv[4];
                ldsm4(bhv[0], bhv[1], bhv[2], bhv[3], uBh + base);
                ldsm4(blv[0], blv[1], blv[2], blv[3], uBl + base);
                #pragma unroll
                for (int half = 0; half < 2; half++) {
                    int nt = pair * 2 + half;
                    mma16(accE[nt], ah[0], ah[1], ah[2], ah[3], bhv[half*2], bhv[half*2+1]);
                    mma16(accE[nt], ah[0], ah[1], ah[2], ah[3], blv[half*2], blv[half*2+1]);
                    mma16(accE[nt], al[0], al[1], al[2], al[3], bhv[half*2], bhv[half*2+1]);
                }
            }
        }
        #pragma unroll
        for (int nt = 0; nt < 4; nt++) {
            int col = chunk * 64 + wn * 32 + nt * 8 + t * 2;
            Gs[ar * 132 + col]           = accE[nt][0];
            Gs[ar * 132 + col + 1]       = accE[nt][1];
            Gs[(ar + 8) * 132 + col]     = accE[nt][2];
            Gs[(ar + 8) * 132 + col + 1] = accE[nt][3];
        }
    }
    __syncthreads();

    #pragma unroll
    for (int nt = 0; nt < 4; nt++) {
        int kb = wn * 32 + nt * 8 + t * 2;
        #pragma unroll
        for (int r4 = 0; r4 < 4; r4++) {
            int q = ar + ((r4 >= 2) ? 8 : 0);
            int k = kb + (r4 & 1);
            int c = k + 63 - q;
            accK[nt][r4] = (accK[nt][r4] + Gs[q * 132 + c]
                            + gUK[bh * NT + k0 + k] + gVE[h * NR + rbase + c]) * 0.125f;
        }
    }

    float m0 = -1e30f, m1 = -1e30f;
    #pragma unroll
    for (int nt = 0; nt < 4; nt++) {
        m0 = fmaxf(m0, fmaxf(accK[nt][0], accK[nt][1]));
        m1 = fmaxf(m1, fmaxf(accK[nt][2], accK[nt][3]));
    }
    m0 = fmaxf(m0, __shfl_xor_sync(0xffffffffu, m0, 1));
    m0 = fmaxf(m0, __shfl_xor_sync(0xffffffffu, m0, 2));
    m1 = fmaxf(m1, __shfl_xor_sync(0xffffffffu, m1, 1));
    m1 = fmaxf(m1, __shfl_xor_sync(0xffffffffu, m1, 2));
    if (t == 0) {
        redM[wn * 64 + ar]     = m0;
        redM[wn * 64 + ar + 8] = m1;
    }
    __syncthreads();
    m0 = fmaxf(redM[ar],     redM[64 + ar]);
    m1 = fmaxf(redM[ar + 8], redM[64 + ar + 8]);

    float sum0 = 0.f, sum1 = 0.f;
    #pragma unroll
    for (int nt = 0; nt < 4; nt++) {
        accK[nt][0] = __expf(accK[nt][0] - m0);
        accK[nt][1] = __expf(accK[nt][1] - m0);
        accK[nt][2] = __expf(accK[nt][2] - m1);
        accK[nt][3] = __expf(accK[nt][3] - m1);
        sum0 += accK[nt][0] + accK[nt][1];
        sum1 += accK[nt][2] + accK[nt][3];
    }
    sum0 += __shfl_xor_sync(0xffffffffu, sum0, 1);
    sum0 += __shfl_xor_sync(0xffffffffu, sum0, 2);
    sum1 += __shfl_xor_sync(0xffffffffu, sum1, 1);
    sum1 += __shfl_xor_sync(0xffffffffu, sum1, 2);
    if (t == 0) {
        redL[wn * 64 + ar]     = sum0;
        redL[wn * 64 + ar + 8] = sum1;
    }
    __syncthreads();
    if (wn == 0 && t == 0) {
        size_t r0 = (size_t)(bh * NT + q0 + ar) * NKT + blockIdx.x;
        size_t r1 = (size_t)(bh * NT + q0 + ar + 8) * NKT + blockIdx.x;
        gPartM[r0] = m0;  gPartL[r0] = redL[ar]     + redL[64 + ar];
        gPartM[r1] = m1;  gPartL[r1] = redL[ar + 8] + redL[64 + ar + 8];
    }

    #pragma unroll
    for (int nt = 0; nt < 4; nt++) {
        int kb = wn * 32 + nt * 8 + t * 2;
        #pragma unroll
        for (int r4 = 0; r4 < 4; r4++) {
            int q = ar + ((r4 >= 2) ? 8 : 0);
            int k = kb + (r4 & 1);
            gS[(size_t)(bh * NT + q0 + q) * NT + k0 + k] = accK[nt][r4];
        }
    }
}

// ---------------- combine per-tile stats -> per-(row,tile) scales --------
__global__ void reduce_kernel() {
    int row = blockIdx.x * 256 + threadIdx.x;
    if (row >= NROWS) return;
    size_t base = (size_t)row * NKT;
    float m = -1e30f;
    float pm[NKT], pl[NKT];
    #pragma unroll
    for (int i = 0; i < NKT; i++) {
        pm[i] = gPartM[base + i];
        pl[i] = gPartL[base + i];
        m = fmaxf(m, pm[i]);
    }
    float l = 0.f;
    #pragma unroll
    for (int i = 0; i < NKT; i++) l += __expf(pm[i] - m) * pl[i];
    float inv = 1.f / l;
    #pragma unroll
    for (int i = 0; i < NKT; i++) gScale[base + i] = __expf(pm[i] - m) * inv;
}

// ---------------- O = P @ V (3xBF16 + ldmatrix), P scaled on load --------
__global__ void pv_tc() {
    extern __shared__ unsigned sm[];
    unsigned* Ph  = sm;                   // 64*PW
    unsigned* Pl  = Ph + 64 * PW;
    unsigned* Vth = Pl + 64 * PW;         // 64*PW, [d][posword]
    unsigned* Vtl = Vth + 64 * PW;
    int tid = threadIdx.x;
    int warp = tid >> 5, lane = tid & 31;
    int wm = warp >> 1, wn = warp & 1;
    int g = lane >> 2, t = lane & 3;
    int bh = blockIdx.y, b = bh >> 3, h = bh & 7;
    int q0 = blockIdx.x * 64;
    float acc[4][4] = {};
    int ar = wm * 16 + g;
    unsigned uPh = smaddr(Ph), uPl = smaddr(Pl), uVh = smaddr(Vth), uVl = smaddr(Vtl);
    unsigned aoff = AOFF(lane), boff = BOFF(lane);
    unsigned abase = ((wm * 16 * PW) << 2) + aoff;

    for (int kk0 = 0; kk0 < NT; kk0 += 64) {
        int ktile = kk0 >> 6;
        #pragma unroll
        for (int i = 0; i < 4; i++) {
            int idx = tid + i * 256;
            int row = idx >> 4, c4 = (idx & 15) << 2;
            float sc = gScale[(size_t)(bh * NT + q0 + row) * NKT + ktile];
            float4 pv = *(const float4*)&gS[(size_t)(bh * NT + q0 + row) * NT + kk0 + c4];
            int w = c4 >> 1;
            unsigned h0, l0, h1, l1;
            cvt_pair2(pv.x * sc, pv.y * sc, h0, l0);
            cvt_pair2(pv.z * sc, pv.w * sc, h1, l1);
            *(uint2*)&Ph[row * PW + w] = make_uint2(h0, h1);
            *(uint2*)&Pl[row * PW + w] = make_uint2(l0, l1);
        }
        #pragma unroll
        for (int i = 0; i < 2; i++) {
            int u = tid + i * 256;
            int p = u >> 4, dg = (u & 15) << 2;
            const float* v0 = &gV[(size_t)(b * NT + kk0 + 2 * p) * ND + h * NDH + dg];
            const float* v1 = v0 + ND;
            float4 a = *(const float4*)v0;
            float4 c = *(const float4*)v1;
            unsigned hv, lv;
            cvt_pair2(a.x, c.x, hv, lv); Vth[(dg + 0) * PW + p] = hv; Vtl[(dg + 0) * PW + p] = lv;
            cvt_pair2(a.y, c.y, hv, lv); Vth[(dg + 1) * PW + p] = hv; Vtl[(dg + 1) * PW + p] = lv;
            cvt_pair2(a.z, c.z, hv, lv); Vth[(dg + 2) * PW + p] = hv; Vtl[(dg + 2) * PW + p] = lv;
            cvt_pair2(a.w, c.w, hv, lv); Vth[(dg + 3) * PW + p] = hv; Vtl[(dg + 3) * PW + p] = lv;
        }
        __syncthreads();
        #pragma unroll
        for (int kw = 0; kw < 32; kw += 8) {
            unsigned ah[4], al[4];
            ldsm4(ah[0], ah[1], ah[2], ah[3], uPh + abase + (kw << 2));
            ldsm4(al[0], al[1], al[2], al[3], uPl + abase + (kw << 2));
            #pragma unroll
            for (int pair = 0; pair < 2; pair++) {
                unsigned base = (((wn * 32 + pair * 16) * PW + kw) << 2) + boff;
                unsigned bhv[4], blv[4];
                ldsm4(bhv[0], bhv[1], bhv[2], bhv[3], uVh + base);
                ldsm4(blv[0], blv[1], blv[2], blv[3], uVl + base);
                #pragma unroll
                for (int half = 0; half < 2; half++) {
                    int nt = pair * 2 + half;
                    mma16(acc[nt], ah[0], ah[1], ah[2], ah[3], bhv[half*2], bhv[half*2+1]);
                    mma16(acc[nt], ah[0], ah[1], ah[2], ah[3], blv[half*2], blv[half*2+1]);
                    mma16(acc[nt], al[0], al[1], al[2], al[3], bhv[half*2], bhv[half*2+1]);
                }
            }
        }
        __syncthreads();
    }
    #pragma unroll
    for (int nt = 0; nt < 4; nt++) {
        int row = q0 + ar;
        int col = wn * 32 + nt * 8 + t * 2;
        gO[(size_t)(b * NT + row) * ND + h * NDH + col]         = acc[nt][0];
        gO[(size_t)(b * NT + row) * ND + h * NDH + col + 1]     = acc[nt][1];
        gO[(size_t)(b * NT + row + 8) * ND + h * NDH + col]     = acc[nt][2];
        gO[(size_t)(b * NT + row + 8) * ND + h * NDH + col + 1] = acc[nt][3];
    }
}

// -------------------------------------------------------------------------
extern "C" void kernel_launch(void* const* d_in, const int* in_sizes, int n_in,
                              void* d_out, int out_size) {
    const float* query = (const float*)d_in[0];
    const float* key_  = (const float*)d_in[1];
    const float* value = (const float*)d_in[2];
    const float* Wq = (const float*)d_in[3];
    const float* bq = (const float*)d_in[4];
    const float* Wk = (const float*)d_in[5];
    const float* bk = (const float*)d_in[6];
    const float* Wv = (const float*)d_in[7];
    const float* bv = (const float*)d_in[8];
    const float* Wp = (const float*)d_in[9];
    const float* bp = (const float*)d_in[10];
    const float* Wo = (const float*)d_in[11];
    const float* bo = (const float*)d_in[12];
    const float* ub = (const float*)d_in[13];
    const float* vb = (const float*)d_in[14];
    float* out = (float*)d_out;

    float *pQ, *pK, *pV, *pPE, *pE, *pO;
    cudaGetSymbolAddress((void**)&pQ, gQ);
    cudaGetSymbolAddress((void**)&pK, gK);
    cudaGetSymbolAddress((void**)&pV, gV);
    cudaGetSymbolAddress((void**)&pPE, gPE);
    cudaGetSymbolAddress((void**)&pE, gE);
    cudaGetSymbolAddress((void**)&pO, gO);

    const int PROJ_SMEM   = (2 * 128 * PW + 2 * 64 * PW) * 4;                // 55296
    const int SCORES_SMEM = (4 * 64 * PW) * 4 + (64 * 132) * 4 + 256 * 4;    // 71680
    const int PV_SMEM     = (4 * 64 * PW) * 4;                               // 36864
    cudaFuncSetAttribute(proj_all,  cudaFuncAttributeMaxDynamicSharedMemorySize, PROJ_SMEM);
    cudaFuncSetAttribute(proj_tc,   cudaFuncAttributeMaxDynamicSharedMemorySize, PROJ_SMEM);
    cudaFuncSetAttribute(scores_tc, cudaFuncAttributeMaxDynamicSharedMemorySize, SCORES_SMEM);
    cudaFuncSetAttribute(pv_tc,     cudaFuncAttributeMaxDynamicSharedMemorySize, PV_SMEM);

    ProjArgs pa;
    pa.A[0] = query; pa.W[0] = Wq; pa.bias[0] = bq; pa.C[0] = pQ; pa.M[0] = NM;
    pa.A[1] = key_;  pa.W[1] = Wk; pa.bias[1] = bk; pa.C[1] = pK; pa.M[1] = NM;
    pa.A[2] = value; pa.W[2] = Wv; pa.bias[2] = bv; pa.C[2] = pV; pa.M[2] = NM;
    pa.A[3] = pPE;   pa.W[3] = Wp; pa.bias[3] = bp; pa.C[3] = pE; pa.M[3] = NR;

    pe_kernel<<<NR, 256>>>();
    proj_all<<<896, 256, PROJ_SMEM>>>(pa);
    ukve_kernel<<<6143, 256>>>(ub, vb);
    scores_tc<<<dim3(16, 16, 32), 256, SCORES_SMEM>>>();
    reduce_kernel<<<128, 256>>>();
    pv_tc<<<dim3(16, 32), 256, PV_SMEM>>>();
    proj_tc<<<dim3(8, 32), 256, PROJ_SMEM>>>(pO, Wo, bo, out, NM);
}

// round 9
// speedup vs baseline: 1.8190x; 1.1150x over previous
#include <cuda_runtime.h>
#include <cuda_bf16.h>
#include <math.h>

// Problem shapes (fixed by the dataset)
#define NB 4
#define NT 1024
#define ND 512
#define NH 8
#define NDH 64
#define NR 2047          // 2*T - 1
#define NM 4096          // B*T
#define NROWS (NB * NH * NT)   // 32768 score rows
#define NKT 8                  // k-tiles of 128 per row

#define PW 36            // padded word-row length (32 data words + 4)
#define GSW 196          // Gs row stride (191 cols + pad)

// ---------------- device scratch (no allocations allowed) ----------------
__device__ float gQ[NM * ND];
__device__ float gK[NM * ND];
__device__ float gV[NM * ND];
__device__ float gPE[NR * ND];
__device__ float gE[NR * ND];
__device__ float gS[33554432];        // B*H*T*T, holds exp(s - m_tile)
__device__ float gO[NM * ND];
__device__ float gUK[NB * NH * NT];
__device__ float gVE[NH * NR];
__device__ float gPartM[NROWS * NKT];
__device__ float gPartL[NROWS * NKT];
__device__ float gScale[NROWS * NKT];

// ---------------- bf16 split helpers ----------------
__device__ __forceinline__ void cvt_pair2(float a, float b, unsigned& hi, unsigned& lo) {
    unsigned ha = __bfloat16_as_ushort(__float2bfloat16(a));
    unsigned hb = __bfloat16_as_ushort(__float2bfloat16(b));
    float ra = a - __bfloat162float(__ushort_as_bfloat16((unsigned short)ha));
    float rb = b - __bfloat162float(__ushort_as_bfloat16((unsigned short)hb));
    unsigned la = __bfloat16_as_ushort(__float2bfloat16(ra));
    unsigned lb = __bfloat16_as_ushort(__float2bfloat16(rb));
    hi = (hb << 16) | ha;
    lo = (lb << 16) | la;
}
__device__ __forceinline__ void mma16(float (&c)[4], unsigned a0, unsigned a1,
                                      unsigned a2, unsigned a3, unsigned b0, unsigned b1) {
    asm volatile(
        "mma.sync.aligned.m16n8k16.row.col.f32.bf16.bf16.f32 "
        "{%0,%1,%2,%3},{%4,%5,%6,%7},{%8,%9},{%0,%1,%2,%3};"
        : "+f"(c[0]), "+f"(c[1]), "+f"(c[2]), "+f"(c[3])
        : "r"(a0), "r"(a1), "r"(a2), "r"(a3), "r"(b0), "r"(b1));
}
__device__ __forceinline__ unsigned smaddr(const void* p) {
    return (unsigned)__cvta_generic_to_shared(p);
}
__device__ __forceinline__ void ldsm4(unsigned& r0, unsigned& r1, unsigned& r2,
                                      unsigned& r3, unsigned a) {
    asm volatile("ldmatrix.sync.aligned.m8n8.x4.shared.b16 {%0,%1,%2,%3}, [%4];"
                 : "=r"(r0), "=r"(r1), "=r"(r2), "=r"(r3) : "r"(a));
}
// A-fragment lane offset (bytes): row = lane&15, +16B for lanes 16-31
#define AOFF(lane) (((((lane) & 15) * PW + ((lane) >> 4) * 4)) << 2)
// B-fragment lane offset (two n-blocks of 8)
#define BOFF(lane) (((((((lane) >> 4) << 3) + ((lane) & 7)) * PW + (((lane) >> 3) & 1) * 4)) << 2)

// ---------------- positional encoding ----------------
__global__ void pe_kernel() {
    int idx = blockIdx.x * 256 + threadIdx.x;
    if (idx >= NR * 256) return;
    int r = idx >> 8;
    int m = idx & 255;
    float inv = exp2f(-(float)m * (13.287712379549449f / 256.0f));
    float ang = (float)(1023 - r) * inv;
    gPE[r * ND + 2 * m]     = (float)sin((double)ang);
    gPE[r * ND + 2 * m + 1] = (float)cos((double)ang);
}

// ---------------- GEMM body (shared by proj_all / proj_tc) ---------------
struct ProjArgs {
    const float* A[4];
    const float* W[4];
    const float* bias[4];
    float*       C[4];
    int          M[4];
};

__device__ __forceinline__ void proj_body(const float* __restrict__ A,
                                          const float* __restrict__ W,
                                          const float* __restrict__ bias,
                                          float* __restrict__ C, int M,
                                          int bx, int by, unsigned* sm) {
    unsigned* Ah = sm;                    // 128*PW
    unsigned* Al = Ah + 128 * PW;
    unsigned* Wh = Al + 128 * PW;         // 64*PW, stored [n][kword]
    unsigned* Wl = Wh + 64 * PW;
    int tid = threadIdx.x;
    int warp = tid >> 5, lane = tid & 31;
    int wm = warp >> 1, wn = warp & 1;
    int g = lane >> 2, t = lane & 3;
    int bm = by * 128, bn = bx * 64;
    float acc[2][4][4] = {};
    unsigned uAh = smaddr(Ah), uAl = smaddr(Al), uWh = smaddr(Wh), uWl = smaddr(Wl);
    unsigned aoff = AOFF(lane), boff = BOFF(lane);

    for (int k0 = 0; k0 < 512; k0 += 64) {
        #pragma unroll
        for (int i = 0; i < 8; i++) {
            int idx = tid + i * 256;
            int row = idx >> 4, c4 = (idx & 15) << 2;
            int grow = bm + row;
            float4 av = (grow < M) ? *(const float4*)&A[(size_t)grow * 512 + k0 + c4]
                                   : make_float4(0.f, 0.f, 0.f, 0.f);
            int w = c4 >> 1;
            unsigned h0, l0, h1, l1;
            cvt_pair2(av.x, av.y, h0, l0);
            cvt_pair2(av.z, av.w, h1, l1);
            *(uint2*)&Ah[row * PW + w] = make_uint2(h0, h1);
            *(uint2*)&Al[row * PW + w] = make_uint2(l0, l1);
        }
        #pragma unroll
        for (int i = 0; i < 4; i++) {
            int idx = tid + i * 256;
            int row = idx >> 4, c4 = (idx & 15) << 2;
            float4 wv = *(const float4*)&W[(size_t)(bn + row) * 512 + k0 + c4];
            int w = c4 >> 1;
            unsigned h0, l0, h1, l1;
            cvt_pair2(wv.x, wv.y, h0, l0);
            cvt_pair2(wv.z, wv.w, h1, l1);
            *(uint2*)&Wh[row * PW + w] = make_uint2(h0, h1);
            *(uint2*)&Wl[row * PW + w] = make_uint2(l0, l1);
        }
        __syncthreads();
        #pragma unroll
        for (int kw = 0; kw < 32; kw += 8) {
            unsigned ah[2][4], al[2][4];
            #pragma unroll
            for (int mt = 0; mt < 2; mt++) {
                unsigned base = (((wm * 32 + mt * 16) * PW + kw) << 2) + aoff;
                ldsm4(ah[mt][0], ah[mt][1], ah[mt][2], ah[mt][3], uAh + base);
                ldsm4(al[mt][0], al[mt][1], al[mt][2], al[mt][3], uAl + base);
            }
            #pragma unroll
            for (int pair = 0; pair < 2; pair++) {
                unsigned base = (((wn * 32 + pair * 16) * PW + kw) << 2) + boff;
                unsigned bh[4], bl[4];
                ldsm4(bh[0], bh[1], bh[2], bh[3], uWh + base);
                ldsm4(bl[0], bl[1], bl[2], bl[3], uWl + base);
                #pragma unroll
                for (int half = 0; half < 2; half++) {
                    int nt = pair * 2 + half;
                    unsigned bh0 = bh[half * 2], bh1 = bh[half * 2 + 1];
                    unsigned bl0 = bl[half * 2], bl1 = bl[half * 2 + 1];
                    #pragma unroll
                    for (int mt = 0; mt < 2; mt++) {
                        mma16(acc[mt][nt], ah[mt][0], ah[mt][1], ah[mt][2], ah[mt][3], bh0, bh1);
                        mma16(acc[mt][nt], ah[mt][0], ah[mt][1], ah[mt][2], ah[mt][3], bl0, bl1);
                        mma16(acc[mt][nt], al[mt][0], al[mt][1], al[mt][2], al[mt][3], bh0, bh1);
                    }
                }
            }
        }
        __syncthreads();
    }
    #pragma unroll
    for (int mt = 0; mt < 2; mt++) {
        #pragma unroll
        for (int nt = 0; nt < 4; nt++) {
            int row = bm + wm * 32 + mt * 16 + g;
            int col = bn + wn * 32 + nt * 8 + t * 2;
            if (row < M) {
                C[(size_t)row * 512 + col]     = acc[mt][nt][0] + bias[col];
                C[(size_t)row * 512 + col + 1] = acc[mt][nt][1] + bias[col + 1];
            }
            if (row + 8 < M) {
                C[(size_t)(row + 8) * 512 + col]     = acc[mt][nt][2] + bias[col];
                C[(size_t)(row + 8) * 512 + col + 1] = acc[mt][nt][3] + bias[col + 1];
            }
        }
    }
}

__global__ void proj_all(ProjArgs a) {
    extern __shared__ unsigned sm[];
    int bid = blockIdx.x;
    int z, bx, by;
    if (bid < 768) { z = bid >> 8; int r = bid & 255; by = r >> 3; bx = r & 7; }
    else           { z = 3;        int r = bid - 768; by = r >> 3; bx = r & 7; }
    proj_body(a.A[z], a.W[z], a.bias[z], a.C[z], a.M[z], bx, by, sm);
}

__global__ void proj_tc(const float* __restrict__ A, const float* __restrict__ W,
                        const float* __restrict__ bias, float* __restrict__ C, int M) {
    extern __shared__ unsigned sm[];
    proj_body(A, W, bias, C, M, blockIdx.x, blockIdx.y, sm);
}

// ---------------- gUK + gVE fused -------------------------------------
__global__ void ukve_kernel(const float* __restrict__ u, const float* __restrict__ v) {
    int gid = blockIdx.x * 256 + threadIdx.x;
    int w = gid >> 5, lane = gid & 31;
    if (w < NB * NH * NT) {
        int t = w & (NT - 1);
        int bh = w >> 10;
        int h = bh & 7, b = bh >> 3;
        const float* kp = gK + (size_t)(b * NT + t) * ND + h * NDH;
        const float* up = u + h * NDH;
        float s = kp[lane] * up[lane] + kp[lane + 32] * up[lane + 32];
        #pragma unroll
        for (int o = 16; o; o >>= 1) s += __shfl_down_sync(0xffffffffu, s, o);
        if (lane == 0) gUK[bh * NT + t] = s;
    } else {
        int w2 = w - NB * NH * NT;
        if (w2 >= NH * NR) return;
        int h = w2 / NR;
        int r = w2 - h * NR;
        const float* ep = gE + (size_t)r * ND + h * NDH;
        const float* vp = v + h * NDH;
        float s = ep[lane] * vp[lane] + ep[lane + 32] * vp[lane + 32];
        #pragma unroll
        for (int o = 16; o; o >>= 1) s += __shfl_down_sync(0xffffffffu, s, o);
        if (lane == 0) gVE[h * NR + r] = s;
    }
}

// ---------------- scores: 64q x 128k tile, 32x32 warp tiles ---------------
// 8 warps in 2m x 4n. QK GEMM + E band (128-col chunk + 64-col chunk) +
// diagonal gather + per-tile softmax stats. Writes exp(s - m_tile) to gS.
__global__ void scores_tc() {
    extern __shared__ unsigned sm[];
    unsigned* Qh = sm;                    // 64*PW
    unsigned* Ql = Qh + 64 * PW;
    unsigned* Bh = Ql + 64 * PW;          // 128*PW (K tile / E chunks)
    unsigned* Bl = Bh + 128 * PW;
    float* Gs   = (float*)(Bl + 128 * PW);// 64*GSW
    float* redM = Gs + 64 * GSW;          // [4][64]
    float* redL = redM + 256;             // [4][64]
    int tid = threadIdx.x;
    int bh = blockIdx.z, h = bh & 7, b = bh >> 3;
    int q0 = blockIdx.y * 64, k0 = blockIdx.x * 128;
    int warp = tid >> 5, lane = tid & 31;
    int wm = warp >> 2, wn = warp & 3;
    int g = lane >> 2, t = lane & 3;
    unsigned uQh = smaddr(Qh), uQl = smaddr(Ql), uBh = smaddr(Bh), uBl = smaddr(Bl);
    unsigned aoff = AOFF(lane), boff = BOFF(lane);

    // ---- load Q (64x64) and K (128x64) ----
    #pragma unroll
    for (int i = 0; i < 4; i++) {
        int idx = tid + i * 256;
        int row = idx >> 4, c4 = (idx & 15) << 2;
        float4 qv = *(const float4*)&gQ[(size_t)(b * NT + q0 + row) * ND + h * NDH + c4];
        int w = c4 >> 1;
        unsigned h0, l0, h1, l1;
        cvt_pair2(qv.x, qv.y, h0, l0);
        cvt_pair2(qv.z, qv.w, h1, l1);
        *(uint2*)&Qh[row * PW + w] = make_uint2(h0, h1);
        *(uint2*)&Ql[row * PW + w] = make_uint2(l0, l1);
    }
    #pragma unroll
    for (int i = 0; i < 8; i++) {
        int idx = tid + i * 256;
        int row = idx >> 4, c4 = (idx & 15) << 2;
        float4 kv = *(const float4*)&gK[(size_t)(b * NT + k0 + row) * ND + h * NDH + c4];
        int w = c4 >> 1;
        unsigned h0, l0, h1, l1;
        cvt_pair2(kv.x, kv.y, h0, l0);
        cvt_pair2(kv.z, kv.w, h1, l1);
        *(uint2*)&Bh[row * PW + w] = make_uint2(h0, h1);
        *(uint2*)&Bl[row * PW + w] = make_uint2(l0, l1);
    }
    __syncthreads();

    // ---- QK GEMM: warp tile 32x32 ----
    float accK[2][4][4] = {};
    #pragma unroll
    for (int kw = 0; kw < 32; kw += 8) {
        unsigned ah[2][4], al[2][4];
        #pragma unroll
        for (int mt = 0; mt < 2; mt++) {
            unsigned base = (((wm * 32 + mt * 16) * PW + kw) << 2) + aoff;
            ldsm4(ah[mt][0], ah[mt][1], ah[mt][2], ah[mt][3], uQh + base);
            ldsm4(al[mt][0], al[mt][1], al[mt][2], al[mt][3], uQl + base);
        }
        #pragma unroll
        for (int pair = 0; pair < 2; pair++) {
            unsigned base = (((wn * 32 + pair * 16) * PW + kw) << 2) + boff;
            unsigned bhv[4], blv[4];
            ldsm4(bhv[0], bhv[1], bhv[2], bhv[3], uBh + base);
            ldsm4(blv[0], blv[1], blv[2], blv[3], uBl + base);
            #pragma unroll
            for (int half = 0; half < 2; half++) {
                int nt = pair * 2 + half;
                #pragma unroll
                for (int mt = 0; mt < 2; mt++) {
                    mma16(accK[mt][nt], ah[mt][0], ah[mt][1], ah[mt][2], ah[mt][3],
                          bhv[half*2], bhv[half*2+1]);
                    mma16(accK[mt][nt], ah[mt][0], ah[mt][1], ah[mt][2], ah[mt][3],
                          blv[half*2], blv[half*2+1]);
                    mma16(accK[mt][nt], al[mt][0], al[mt][1], al[mt][2], al[mt][3],
                          bhv[half*2], bhv[half*2+1]);
                }
            }
        }
    }

    int rbase = 960 + k0 - q0;   // >= 0 always; r = rbase + c, c = k + 63 - q

    // ---- E chunk0: band cols 0..127 (E rows rbase..rbase+127) ----
    __syncthreads();
    #pragma unroll
    for (int i = 0; i < 8; i++) {
        int idx = tid + i * 256;
        int row = idx >> 4, c4 = (idx & 15) << 2;
        int r = rbase + row;
        float4 ev = (r < NR) ? *(const float4*)&gE[(size_t)r * ND + h * NDH + c4]
                             : make_float4(0.f, 0.f, 0.f, 0.f);
        int w = c4 >> 1;
        unsigned h0, l0, h1, l1;
        cvt_pair2(ev.x, ev.y, h0, l0);
        cvt_pair2(ev.z, ev.w, h1, l1);
        *(uint2*)&Bh[row * PW + w] = make_uint2(h0, h1);
        *(uint2*)&Bl[row * PW + w] = make_uint2(l0, l1);
    }
    __syncthreads();
    {
        float accE[2][4][4] = {};
        #pragma unroll
        for (int kw = 0; kw < 32; kw += 8) {
            unsigned ah[2][4], al[2][4];
            #pragma unroll
            for (int mt = 0; mt < 2; mt++) {
                unsigned base = (((wm * 32 + mt * 16) * PW + kw) << 2) + aoff;
                ldsm4(ah[mt][0], ah[mt][1], ah[mt][2], ah[mt][3], uQh + base);
                ldsm4(al[mt][0], al[mt][1], al[mt][2], al[mt][3], uQl + base);
            }
            #pragma unroll
            for (int pair = 0; pair < 2; pair++) {
                unsigned base = (((wn * 32 + pair * 16) * PW + kw) << 2) + boff;
                unsigned bhv[4], blv[4];
                ldsm4(bhv[0], bhv[1], bhv[2], bhv[3], uBh + base);
                ldsm4(blv[0], blv[1], blv[2], blv[3], uBl + base);
                #pragma unroll
                for (int half = 0; half < 2; half++) {
                    int nt = pair * 2 + half;
                    #pragma unroll
                    for (int mt = 0; mt < 2; mt++) {
                        mma16(accE[mt][nt], ah[mt][0], ah[mt][1], ah[mt][2], ah[mt][3],
                              bhv[half*2], bhv[half*2+1]);
                        mma16(accE[mt][nt], ah[mt][0], ah[mt][1], ah[mt][2], ah[mt][3],
                              blv[half*2], blv[half*2+1]);
                        mma16(accE[mt][nt], al[mt][0], al[mt][1], al[mt][2], al[mt][3],
                              bhv[half*2], bhv[half*2+1]);
                    }
                }
            }
        }
        #pragma unroll
        for (int mt = 0; mt < 2; mt++)
            #pragma unroll
            for (int nt = 0; nt < 4; nt++) {
                int row = wm * 32 + mt * 16 + g;
                int col = wn * 32 + nt * 8 + t * 2;
                Gs[row * GSW + col]           = accE[mt][nt][0];
                Gs[row * GSW + col + 1]       = accE[mt][nt][1];
                Gs[(row + 8) * GSW + col]     = accE[mt][nt][2];
                Gs[(row + 8) * GSW + col + 1] = accE[mt][nt][3];
            }
    }

    // ---- E chunk1: band cols 128..191 (E rows rbase+128..+191), warp n=16 ----
    __syncthreads();
    #pragma unroll
    for (int i = 0; i < 4; i++) {
        int idx = tid + i * 256;
        int row = idx >> 4, c4 = (idx & 15) << 2;
        int r = rbase + 128 + row;
        float4 ev = (r < NR) ? *(const float4*)&gE[(size_t)r * ND + h * NDH + c4]
                             : make_float4(0.f, 0.f, 0.f, 0.f);
        int w = c4 >> 1;
        unsigned h0, l0, h1, l1;
        cvt_pair2(ev.x, ev.y, h0, l0);
        cvt_pair2(ev.z, ev.w, h1, l1);
        *(uint2*)&Bh[row * PW + w] = make_uint2(h0, h1);
        *(uint2*)&Bl[row * PW + w] = make_uint2(l0, l1);
    }
    __syncthreads();
    {
        float accF[2][2][4] = {};
        #pragma unroll
        for (int kw = 0; kw < 32; kw += 8) {
            unsigned ah[2][4], al[2][4];
            #pragma unroll
            for (int mt = 0; mt < 2; mt++) {
                unsigned base = (((wm * 32 + mt * 16) * PW + kw) << 2) + aoff;
                ldsm4(ah[mt][0], ah[mt][1], ah[mt][2], ah[mt][3], uQh + base);
                ldsm4(al[mt][0], al[mt][1], al[mt][2], al[mt][3], uQl + base);
            }
            unsigned base = (((wn * 16) * PW + kw) << 2) + boff;
            unsigned bhv[4], blv[4];
            ldsm4(bhv[0], bhv[1], bhv[2], bhv[3], uBh + base);
            ldsm4(blv[0], blv[1], blv[2], blv[3], uBl + base);
            #pragma unroll
            for (int half = 0; half < 2; half++) {
                #pragma unroll
                for (int mt = 0; mt < 2; mt++) {
                    mma16(accF[mt][half], ah[mt][0], ah[mt][1], ah[mt][2], ah[mt][3],
                          bhv[half*2], bhv[half*2+1]);
                    mma16(accF[mt][half], ah[mt][0], ah[mt][1], ah[mt][2], ah[mt][3],
                          blv[half*2], blv[half*2+1]);
                    mma16(accF[mt][half], al[mt][0], al[mt][1], al[mt][2], al[mt][3],
                          bhv[half*2], bhv[half*2+1]);
                }
            }
        }
        #pragma unroll
        for (int mt = 0; mt < 2; mt++)
            #pragma unroll
            for (int nt = 0; nt < 2; nt++) {
                int row = wm * 32 + mt * 16 + g;
                int col = 128 + wn * 16 + nt * 8 + t * 2;
                Gs[row * GSW + col]           = accF[mt][nt][0];
                Gs[row * GSW + col + 1]       = accF[mt][nt][1];
                Gs[(row + 8) * GSW + col]     = accF[mt][nt][2];
                Gs[(row + 8) * GSW + col + 1] = accF[mt][nt][3];
            }
    }
    __syncthreads();

    // ---- gather full raw scores ----
    #pragma unroll
    for (int mt = 0; mt < 2; mt++)
        #pragma unroll
        for (int nt = 0; nt < 4; nt++) {
            int kb = wn * 32 + nt * 8 + t * 2;
            #pragma unroll
            for (int r4 = 0; r4 < 4; r4++) {
                int q = wm * 32 + mt * 16 + g + ((r4 >= 2) ? 8 : 0);
                int k = kb + (r4 & 1);
                int c = k + 63 - q;
                accK[mt][nt][r4] = (accK[mt][nt][r4] + Gs[q * GSW + c]
                                    + gUK[bh * NT + k0 + k] + gVE[h * NR + rbase + c]) * 0.125f;
            }
        }

    // ---- per-tile row stats: thread covers 4 rows (mt x half) ----
    float mrow[2][2];
    #pragma unroll
    for (int mt = 0; mt < 2; mt++) {
        mrow[mt][0] = -1e30f; mrow[mt][1] = -1e30f;
        #pragma unroll
        for (int nt = 0; nt < 4; nt++) {
            mrow[mt][0] = fmaxf(mrow[mt][0], fmaxf(accK[mt][nt][0], accK[mt][nt][1]));
            mrow[mt][1] = fmaxf(mrow[mt][1], fmaxf(accK[mt][nt][2], accK[mt][nt][3]));
        }
        #pragma unroll
        for (int hf = 0; hf < 2; hf++) {
            mrow[mt][hf] = fmaxf(mrow[mt][hf], __shfl_xor_sync(0xffffffffu, mrow[mt][hf], 1));
            mrow[mt][hf] = fmaxf(mrow[mt][hf], __shfl_xor_sync(0xffffffffu, mrow[mt][hf], 2));
        }
    }
    if (t == 0) {
        #pragma unroll
        for (int mt = 0; mt < 2; mt++)
            #pragma unroll
            for (int hf = 0; hf < 2; hf++)
                redM[wn * 64 + wm * 32 + mt * 16 + g + hf * 8] = mrow[mt][hf];
    }
    __syncthreads();
    #pragma unroll
    for (int mt = 0; mt < 2; mt++)
        #pragma unroll
        for (int hf = 0; hf < 2; hf++) {
            int row = wm * 32 + mt * 16 + g + hf * 8;
            mrow[mt][hf] = fmaxf(fmaxf(redM[row], redM[64 + row]),
                                 fmaxf(redM[128 + row], redM[192 + row]));
        }

    float srow[2][2] = {};
    #pragma unroll
    for (int mt = 0; mt < 2; mt++)
        #pragma unroll
        for (int nt = 0; nt < 4; nt++) {
            accK[mt][nt][0] = __expf(accK[mt][nt][0] - mrow[mt][0]);
            accK[mt][nt][1] = __expf(accK[mt][nt][1] - mrow[mt][0]);
            accK[mt][nt][2] = __expf(accK[mt][nt][2] - mrow[mt][1]);
            accK[mt][nt][3] = __expf(accK[mt][nt][3] - mrow[mt][1]);
            srow[mt][0] += accK[mt][nt][0] + accK[mt][nt][1];
            srow[mt][1] += accK[mt][nt][2] + accK[mt][nt][3];
        }
    #pragma unroll
    for (int mt = 0; mt < 2; mt++)
        #pragma unroll
        for (int hf = 0; hf < 2; hf++) {
            srow[mt][hf] += __shfl_xor_sync(0xffffffffu, srow[mt][hf], 1);
            srow[mt][hf] += __shfl_xor_sync(0xffffffffu, srow[mt][hf], 2);
        }
    if (t == 0) {
        #pragma unroll
        for (int mt = 0; mt < 2; mt++)
            #pragma unroll
            for (int hf = 0; hf < 2; hf++)
                redL[wn * 64 + wm * 32 + mt * 16 + g + hf * 8] = srow[mt][hf];
    }
    __syncthreads();
    if (wn == 0 && t == 0) {
        #pragma unroll
        for (int mt = 0; mt < 2; mt++)
            #pragma unroll
            for (int hf = 0; hf < 2; hf++) {
                int row = wm * 32 + mt * 16 + g + hf * 8;
                size_t ri = (size_t)(bh * NT + q0 + row) * NKT + blockIdx.x;
                gPartM[ri] = mrow[mt][hf];
                gPartL[ri] = redL[row] + redL[64 + row] + redL[128 + row] + redL[192 + row];
            }
    }

    // ---- store exp values ----
    #pragma unroll
    for (int mt = 0; mt < 2; mt++)
        #pragma unroll
        for (int nt = 0; nt < 4; nt++) {
            int kb = wn * 32 + nt * 8 + t * 2;
            #pragma unroll
            for (int r4 = 0; r4 < 4; r4++) {
                int q = wm * 32 + mt * 16 + g + ((r4 >= 2) ? 8 : 0);
                int k = kb + (r4 & 1);
                gS[(size_t)(bh * NT + q0 + q) * NT + k0 + k] = accK[mt][nt][r4];
            }
        }
}

// ---------------- combine per-tile stats -> per-(row,tile) scales --------
__global__ void reduce_kernel() {
    int row = blockIdx.x * 256 + threadIdx.x;
    if (row >= NROWS) return;
    size_t base = (size_t)row * NKT;
    float m = -1e30f;
    float pm[NKT], pl[NKT];
    #pragma unroll
    for (int i = 0; i < NKT; i++) {
        pm[i] = gPartM[base + i];
        pl[i] = gPartL[base + i];
        m = fmaxf(m, pm[i]);
    }
    float l = 0.f;
    #pragma unroll
    for (int i = 0; i < NKT; i++) l += __expf(pm[i] - m) * pl[i];
    float inv = 1.f / l;
    #pragma unroll
    for (int i = 0; i < NKT; i++) gScale[base + i] = __expf(pm[i] - m) * inv;
}

// ---------------- O = P @ V: 128 thr, 4 warps, 32x32 warp tiles ----------
__global__ void pv_tc() {
    extern __shared__ unsigned sm[];
    unsigned* Ph  = sm;                   // 64*PW
    unsigned* Pl  = Ph + 64 * PW;
    unsigned* Vth = Pl + 64 * PW;         // 64*PW, [d][posword]
    unsigned* Vtl = Vth + 64 * PW;
    int tid = threadIdx.x;
    int warp = tid >> 5, lane = tid & 31;
    int wm = warp >> 1, wn = warp & 1;
    int g = lane >> 2, t = lane & 3;
    int bh = blockIdx.y, b = bh >> 3, h = bh & 7;
    int q0 = blockIdx.x * 64;
    float acc[2][4][4] = {};
    unsigned uPh = smaddr(Ph), uPl = smaddr(Pl), uVh = smaddr(Vth), uVl = smaddr(Vtl);
    unsigned aoff = AOFF(lane), boff = BOFF(lane);

    for (int kk0 = 0; kk0 < NT; kk0 += 64) {
        int kt8 = kk0 >> 7;
        #pragma unroll
        for (int i = 0; i < 8; i++) {
            int idx = tid + i * 128;
            int row = idx >> 4, c4 = (idx & 15) << 2;
            float sc = gScale[(size_t)(bh * NT + q0 + row) * NKT + kt8];
            float4 pv = *(const float4*)&gS[(size_t)(bh * NT + q0 + row) * NT + kk0 + c4];
            int w = c4 >> 1;
            unsigned h0, l0, h1, l1;
            cvt_pair2(pv.x * sc, pv.y * sc, h0, l0);
            cvt_pair2(pv.z * sc, pv.w * sc, h1, l1);
            *(uint2*)&Ph[row * PW + w] = make_uint2(h0, h1);
            *(uint2*)&Pl[row * PW + w] = make_uint2(l0, l1);
        }
        #pragma unroll
        for (int i = 0; i < 4; i++) {
            int u = tid + i * 128;
            int p = u >> 4, dg = (u & 15) << 2;
            const float* v0 = &gV[(size_t)(b * NT + kk0 + 2 * p) * ND + h * NDH + dg];
            const float* v1 = v0 + ND;
            float4 a = *(const float4*)v0;
            float4 c = *(const float4*)v1;
            unsigned hv, lv;
            cvt_pair2(a.x, c.x, hv, lv); Vth[(dg + 0) * PW + p] = hv; Vtl[(dg + 0) * PW + p] = lv;
            cvt_pair2(a.y, c.y, hv, lv); Vth[(dg + 1) * PW + p] = hv; Vtl[(dg + 1) * PW + p] = lv;
            cvt_pair2(a.z, c.z, hv, lv); Vth[(dg + 2) * PW + p] = hv; Vtl[(dg + 2) * PW + p] = lv;
            cvt_pair2(a.w, c.w, hv, lv); Vth[(dg + 3) * PW + p] = hv; Vtl[(dg + 3) * PW + p] = lv;
        }
        __syncthreads();
        #pragma unroll
        for (int kw = 0; kw < 32; kw += 8) {
            unsigned ah[2][4], al[2][4];
            #pragma unroll
            for (int mt = 0; mt < 2; mt++) {
                unsigned base = (((wm * 32 + mt * 16) * PW + kw) << 2) + aoff;
                ldsm4(ah[mt][0], ah[mt][1], ah[mt][2], ah[mt][3], uPh + base);
                ldsm4(al[mt][0], al[mt][1], al[mt][2], al[mt][3], uPl + base);
            }
            #pragma unroll
            for (int pair = 0; pair < 2; pair++) {
                unsigned base = (((wn * 32 + pair * 16) * PW + kw) << 2) + boff;
                unsigned bhv[4], blv[4];
                ldsm4(bhv[0], bhv[1], bhv[2], bhv[3], uVh + base);
                ldsm4(blv[0], blv[1], blv[2], blv[3], uVl + base);
                #pragma unroll
                for (int half = 0; half < 2; half++) {
                    int nt = pair * 2 + half;
                    #pragma unroll
                    for (int mt = 0; mt < 2; mt++) {
                        mma16(acc[mt][nt], ah[mt][0], ah[mt][1], ah[mt][2], ah[mt][3],
                              bhv[half*2], bhv[half*2+1]);
                        mma16(acc[mt][nt], ah[mt][0], ah[mt][1], ah[mt][2], ah[mt][3],
                              blv[half*2], blv[half*2+1]);
                        mma16(acc[mt][nt], al[mt][0], al[mt][1], al[mt][2], al[mt][3],
                              bhv[half*2], bhv[half*2+1]);
                    }
                }
            }
        }
        __syncthreads();
    }
    #pragma unroll
    for (int mt = 0; mt < 2; mt++)
        #pragma unroll
        for (int nt = 0; nt < 4; nt++) {
            int row = q0 + wm * 32 + mt * 16 + g;
            int col = wn * 32 + nt * 8 + t * 2;
            gO[(size_t)(b * NT + row) * ND + h * NDH + col]         = acc[mt][nt][0];
            gO[(size_t)(b * NT + row) * ND + h * NDH + col + 1]     = acc[mt][nt][1];
            gO[(size_t)(b * NT + row + 8) * ND + h * NDH + col]     = acc[mt][nt][2];
            gO[(size_t)(b * NT + row + 8) * ND + h * NDH + col + 1] = acc[mt][nt][3];
        }
}

// -------------------------------------------------------------------------
extern "C" void kernel_launch(void* const* d_in, const int* in_sizes, int n_in,
                              void* d_out, int out_size) {
    const float* query = (const float*)d_in[0];
    const float* key_  = (const float*)d_in[1];
    const float* value = (const float*)d_in[2];
    const float* Wq = (const float*)d_in[3];
    const float* bq = (const float*)d_in[4];
    const float* Wk = (const float*)d_in[5];
    const float* bk = (const float*)d_in[6];
    const float* Wv = (const float*)d_in[7];
    const float* bv = (const float*)d_in[8];
    const float* Wp = (const float*)d_in[9];
    const float* bp = (const float*)d_in[10];
    const float* Wo = (const float*)d_in[11];
    const float* bo = (const float*)d_in[12];
    const float* ub = (const float*)d_in[13];
    const float* vb = (const float*)d_in[14];
    float* out = (float*)d_out;

    float *pQ, *pK, *pV, *pPE, *pE, *pO;
    cudaGetSymbolAddress((void**)&pQ, gQ);
    cudaGetSymbolAddress((void**)&pK, gK);
    cudaGetSymbolAddress((void**)&pV, gV);
    cudaGetSymbolAddress((void**)&pPE, gPE);
    cudaGetSymbolAddress((void**)&pE, gE);
    cudaGetSymbolAddress((void**)&pO, gO);

    const int PROJ_SMEM   = (2 * 128 * PW + 2 * 64 * PW) * 4;                     // 55296
    const int SCORES_SMEM = (2 * 64 * PW + 2 * 128 * PW + 64 * GSW + 512) * 4;    // 107520
    const int PV_SMEM     = (4 * 64 * PW) * 4;                                    // 36864
    cudaFuncSetAttribute(proj_all,  cudaFuncAttributeMaxDynamicSharedMemorySize, PROJ_SMEM);
    cudaFuncSetAttribute(proj_tc,   cudaFuncAttributeMaxDynamicSharedMemorySize, PROJ_SMEM);
    cudaFuncSetAttribute(scores_tc, cudaFuncAttributeMaxDynamicSharedMemorySize, SCORES_SMEM);
    cudaFuncSetAttribute(pv_tc,     cudaFuncAttributeMaxDynamicSharedMemorySize, PV_SMEM);

    ProjArgs pa;
    pa.A[0] = query; pa.W[0] = Wq; pa.bias[0] = bq; pa.C[0] = pQ; pa.M[0] = NM;
    pa.A[1] = key_;  pa.W[1] = Wk; pa.bias[1] = bk; pa.C[1] = pK; pa.M[1] = NM;
    pa.A[2] = value; pa.W[2] = Wv; pa.bias[2] = bv; pa.C[2] = pV; pa.M[2] = NM;
    pa.A[3] = pPE;   pa.W[3] = Wp; pa.bias[3] = bp; pa.C[3] = pE; pa.M[3] = NR;

    pe_kernel<<<NR, 256>>>();
    proj_all<<<896, 256, PROJ_SMEM>>>(pa);
    ukve_kernel<<<6143, 256>>>(ub, vb);
    scores_tc<<<dim3(8, 16, 32), 256, SCORES_SMEM>>>();
    reduce_kernel<<<128, 256>>>();
    pv_tc<<<dim3(16, 32), 128, PV_SMEM>>>();
    proj_tc<<<dim3(8, 32), 256, PROJ_SMEM>>>(pO, Wo, bo, out, NM);
}

// round 10
// speedup vs baseline: 1.8748x; 1.0307x over previous
#include <cuda_runtime.h>
#include <cuda_bf16.h>
#include <math.h>

// Problem shapes (fixed by the dataset)
#define NB 4
#define NT 1024
#define ND 512
#define NH 8
#define NDH 64
#define NR 2047          // 2*T - 1
#define NM 4096          // B*T
#define NROWS (NB * NH * NT)   // 32768 score rows
#define NKT 8                  // k-tiles of 128 per row
#define NW 256                 // words per row (512 floats / 2)

#define PW 36            // padded word-row length (32 data words + 4)
#define GSW 196          // Gs row stride (191 cols + pad)

// ---------------- device scratch (no allocations allowed) ----------------
__device__ unsigned gQh[NM * NW];
__device__ unsigned gQl[NM * NW];
__device__ unsigned gKh[NM * NW];
__device__ unsigned gKl[NM * NW];
__device__ unsigned gEh[NR * NW];
__device__ unsigned gEl[NR * NW];
__device__ float gV[NM * ND];
__device__ float gPE[NR * ND];
__device__ float gS[33554432];        // B*H*T*T, holds exp(s - m_tile)
__device__ float gO[NM * ND];
__device__ float gUK[NB * NH * NT];
__device__ float gVE[NH * NR];
__device__ float gPartM[NROWS * NKT];
__device__ float gPartL[NROWS * NKT];
__device__ float gScale[NROWS * NKT];

// ---------------- bf16 split helpers ----------------
__device__ __forceinline__ void cvt_pair2(float a, float b, unsigned& hi, unsigned& lo) {
    unsigned ha = __bfloat16_as_ushort(__float2bfloat16(a));
    unsigned hb = __bfloat16_as_ushort(__float2bfloat16(b));
    float ra = a - __bfloat162float(__ushort_as_bfloat16((unsigned short)ha));
    float rb = b - __bfloat162float(__ushort_as_bfloat16((unsigned short)hb));
    unsigned la = __bfloat16_as_ushort(__float2bfloat16(ra));
    unsigned lb = __bfloat16_as_ushort(__float2bfloat16(rb));
    hi = (hb << 16) | ha;
    lo = (lb << 16) | la;
}
__device__ __forceinline__ float2 unpack2(unsigned w) {
    return make_float2(__bfloat162float(__ushort_as_bfloat16((unsigned short)(w & 0xffff))),
                       __bfloat162float(__ushort_as_bfloat16((unsigned short)(w >> 16))));
}
__device__ __forceinline__ void mma16(float (&c)[4], unsigned a0, unsigned a1,
                                      unsigned a2, unsigned a3, unsigned b0, unsigned b1) {
    asm volatile(
        "mma.sync.aligned.m16n8k16.row.col.f32.bf16.bf16.f32 "
        "{%0,%1,%2,%3},{%4,%5,%6,%7},{%8,%9},{%0,%1,%2,%3};"
        : "+f"(c[0]), "+f"(c[1]), "+f"(c[2]), "+f"(c[3])
        : "r"(a0), "r"(a1), "r"(a2), "r"(a3), "r"(b0), "r"(b1));
}
__device__ __forceinline__ unsigned smaddr(const void* p) {
    return (unsigned)__cvta_generic_to_shared(p);
}
__device__ __forceinline__ void ldsm4(unsigned& r0, unsigned& r1, unsigned& r2,
                                      unsigned& r3, unsigned a) {
    asm volatile("ldmatrix.sync.aligned.m8n8.x4.shared.b16 {%0,%1,%2,%3}, [%4];"
                 : "=r"(r0), "=r"(r1), "=r"(r2), "=r"(r3) : "r"(a));
}
// A-fragment lane offset (bytes): row = lane&15, +16B for lanes 16-31
#define AOFF(lane) (((((lane) & 15) * PW + ((lane) >> 4) * 4)) << 2)
// B-fragment lane offset (two n-blocks of 8)
#define BOFF(lane) (((((((lane) >> 4) << 3) + ((lane) & 7)) * PW + (((lane) >> 3) & 1) * 4)) << 2)

// ---------------- positional encoding ----------------
__global__ void pe_kernel() {
    int idx = blockIdx.x * 256 + threadIdx.x;
    if (idx >= NR * 256) return;
    int r = idx >> 8;
    int m = idx & 255;
    float inv = exp2f(-(float)m * (13.287712379549449f / 256.0f));
    float ang = (float)(1023 - r) * inv;
    gPE[r * ND + 2 * m]     = (float)sin((double)ang);
    gPE[r * ND + 2 * m + 1] = (float)cos((double)ang);
}

// ---------------- GEMM body -------------------------------------------
// SPLIT=true: write hi/lo bf16x2 word arrays; else fp32.
struct ProjArgs {
    const float* A[4];
    const float* W[4];
    const float* bias[4];
    unsigned*    Ch[4];   // split outputs (z != 2)
    unsigned*    Cl[4];
    float*       Cf[4];   // fp32 output (z == 2)
    int          M[4];
    int          split[4];
};

__device__ __forceinline__ void proj_body(const float* __restrict__ A,
                                          const float* __restrict__ W,
                                          const float* __restrict__ bias,
                                          unsigned* Ch, unsigned* Cl, float* Cf,
                                          int M, int do_split,
                                          int bx, int by, unsigned* sm) {
    unsigned* Ah = sm;                    // 128*PW
    unsigned* Al = Ah + 128 * PW;
    unsigned* Wh = Al + 128 * PW;         // 64*PW, stored [n][kword]
    unsigned* Wl = Wh + 64 * PW;
    int tid = threadIdx.x;
    int warp = tid >> 5, lane = tid & 31;
    int wm = warp >> 1, wn = warp & 1;
    int g = lane >> 2, t = lane & 3;
    int bm = by * 128, bn = bx * 64;
    float acc[2][4][4] = {};
    unsigned uAh = smaddr(Ah), uAl = smaddr(Al), uWh = smaddr(Wh), uWl = smaddr(Wl);
    unsigned aoff = AOFF(lane), boff = BOFF(lane);

    for (int k0 = 0; k0 < 512; k0 += 64) {
        #pragma unroll
        for (int i = 0; i < 8; i++) {
            int idx = tid + i * 256;
            int row = idx >> 4, c4 = (idx & 15) << 2;
            int grow = bm + row;
            float4 av = (grow < M) ? *(const float4*)&A[(size_t)grow * 512 + k0 + c4]
                                   : make_float4(0.f, 0.f, 0.f, 0.f);
            int w = c4 >> 1;
            unsigned h0, l0, h1, l1;
            cvt_pair2(av.x, av.y, h0, l0);
            cvt_pair2(av.z, av.w, h1, l1);
            *(uint2*)&Ah[row * PW + w] = make_uint2(h0, h1);
            *(uint2*)&Al[row * PW + w] = make_uint2(l0, l1);
        }
        #pragma unroll
        for (int i = 0; i < 4; i++) {
            int idx = tid + i * 256;
            int row = idx >> 4, c4 = (idx & 15) << 2;
            float4 wv = *(const float4*)&W[(size_t)(bn + row) * 512 + k0 + c4];
            int w = c4 >> 1;
            unsigned h0, l0, h1, l1;
            cvt_pair2(wv.x, wv.y, h0, l0);
            cvt_pair2(wv.z, wv.w, h1, l1);
            *(uint2*)&Wh[row * PW + w] = make_uint2(h0, h1);
            *(uint2*)&Wl[row * PW + w] = make_uint2(l0, l1);
        }
        __syncthreads();
        #pragma unroll
        for (int kw = 0; kw < 32; kw += 8) {
            unsigned ah[2][4], al[2][4];
            #pragma unroll
            for (int mt = 0; mt < 2; mt++) {
                unsigned base = (((wm * 32 + mt * 16) * PW + kw) << 2) + aoff;
                ldsm4(ah[mt][0], ah[mt][1], ah[mt][2], ah[mt][3], uAh + base);
                ldsm4(al[mt][0], al[mt][1], al[mt][2], al[mt][3], uAl + base);
            }
            #pragma unroll
            for (int pair = 0; pair < 2; pair++) {
                unsigned base = (((wn * 32 + pair * 16) * PW + kw) << 2) + boff;
                unsigned bh[4], bl[4];
                ldsm4(bh[0], bh[1], bh[2], bh[3], uWh + base);
                ldsm4(bl[0], bl[1], bl[2], bl[3], uWl + base);
                #pragma unroll
                for (int half = 0; half < 2; half++) {
                    int nt = pair * 2 + half;
                    unsigned bh0 = bh[half * 2], bh1 = bh[half * 2 + 1];
                    unsigned bl0 = bl[half * 2], bl1 = bl[half * 2 + 1];
                    #pragma unroll
                    for (int mt = 0; mt < 2; mt++) {
                        mma16(acc[mt][nt], ah[mt][0], ah[mt][1], ah[mt][2], ah[mt][3], bh0, bh1);
                        mma16(acc[mt][nt], ah[mt][0], ah[mt][1], ah[mt][2], ah[mt][3], bl0, bl1);
                        mma16(acc[mt][nt], al[mt][0], al[mt][1], al[mt][2], al[mt][3], bh0, bh1);
                    }
                }
            }
        }
        __syncthreads();
    }
    #pragma unroll
    for (int mt = 0; mt < 2; mt++) {
        #pragma unroll
        for (int nt = 0; nt < 4; nt++) {
            int row = bm + wm * 32 + mt * 16 + g;
            int col = bn + wn * 32 + nt * 8 + t * 2;
            float f0 = acc[mt][nt][0] + bias[col];
            float f1 = acc[mt][nt][1] + bias[col + 1];
            float f2 = acc[mt][nt][2] + bias[col];
            float f3 = acc[mt][nt][3] + bias[col + 1];
            if (do_split) {
                unsigned h0, l0;
                if (row < M) {
                    cvt_pair2(f0, f1, h0, l0);
                    Ch[(size_t)row * NW + (col >> 1)] = h0;
                    Cl[(size_t)row * NW + (col >> 1)] = l0;
                }
                if (row + 8 < M) {
                    cvt_pair2(f2, f3, h0, l0);
                    Ch[(size_t)(row + 8) * NW + (col >> 1)] = h0;
                    Cl[(size_t)(row + 8) * NW + (col >> 1)] = l0;
                }
            } else {
                if (row < M) {
                    Cf[(size_t)row * 512 + col]     = f0;
                    Cf[(size_t)row * 512 + col + 1] = f1;
                }
                if (row + 8 < M) {
                    Cf[(size_t)(row + 8) * 512 + col]     = f2;
                    Cf[(size_t)(row + 8) * 512 + col + 1] = f3;
                }
            }
        }
    }
}

__global__ void proj_all(ProjArgs a) {
    extern __shared__ unsigned sm[];
    int bid = blockIdx.x;
    int z, bx, by;
    if (bid < 768) { z = bid >> 8; int r = bid & 255; by = r >> 3; bx = r & 7; }
    else           { z = 3;        int r = bid - 768; by = r >> 3; bx = r & 7; }
    proj_body(a.A[z], a.W[z], a.bias[z], a.Ch[z], a.Cl[z], a.Cf[z], a.M[z], a.split[z],
              bx, by, sm);
}

__global__ void proj_out(const float* __restrict__ A, const float* __restrict__ W,
                         const float* __restrict__ bias, float* __restrict__ C, int M) {
    extern __shared__ unsigned sm[];
    proj_body(A, W, bias, 0, 0, C, M, 0, blockIdx.x, blockIdx.y, sm);
}

// ---------------- gUK + gVE fused (from split arrays) ------------------
__global__ void ukve_kernel(const float* __restrict__ u, const float* __restrict__ v) {
    int gid = blockIdx.x * 256 + threadIdx.x;
    int w = gid >> 5, lane = gid & 31;
    if (w < NB * NH * NT) {
        int t = w & (NT - 1);
        int bh = w >> 10;
        int h = bh & 7, b = bh >> 3;
        size_t base = (size_t)(b * NT + t) * NW + h * 32 + lane;
        float2 kh = unpack2(gKh[base]);
        float2 kl = unpack2(gKl[base]);
        const float* up = u + h * NDH;
        float s = (kh.x + kl.x) * up[2 * lane] + (kh.y + kl.y) * up[2 * lane + 1];
        #pragma unroll
        for (int o = 16; o; o >>= 1) s += __shfl_down_sync(0xffffffffu, s, o);
        if (lane == 0) gUK[bh * NT + t] = s;
    } else {
        int w2 = w - NB * NH * NT;
        if (w2 >= NH * NR) return;
        int h = w2 / NR;
        int r = w2 - h * NR;
        size_t base = (size_t)r * NW + h * 32 + lane;
        float2 eh = unpack2(gEh[base]);
        float2 el = unpack2(gEl[base]);
        const float* vp = v + h * NDH;
        float s = (eh.x + el.x) * vp[2 * lane] + (eh.y + el.y) * vp[2 * lane + 1];
        #pragma unroll
        for (int o = 16; o; o >>= 1) s += __shfl_down_sync(0xffffffffu, s, o);
        if (lane == 0) gVE[h * NR + r] = s;
    }
}

// ---------------- scores: 64q x 128k, 32x32 warp tiles, pre-split ops -----
__global__ void scores_tc() {
    extern __shared__ unsigned sm[];
    unsigned* Qh = sm;                    // 64*PW
    unsigned* Ql = Qh + 64 * PW;
    unsigned* Bh = Ql + 64 * PW;          // 128*PW (K tile / E chunks)
    unsigned* Bl = Bh + 128 * PW;
    float* Gs   = (float*)(Bl + 128 * PW);// 64*GSW
    float* redM = Gs + 64 * GSW;          // [4][64]
    float* redL = redM + 256;             // [4][64]
    int tid = threadIdx.x;
    int bh = blockIdx.z, h = bh & 7, b = bh >> 3;
    int q0 = blockIdx.y * 64, k0 = blockIdx.x * 128;
    int warp = tid >> 5, lane = tid & 31;
    int wm = warp >> 2, wn = warp & 3;
    int g = lane >> 2, t = lane & 3;
    unsigned uQh = smaddr(Qh), uQl = smaddr(Ql), uBh = smaddr(Bh), uBl = smaddr(Bl);
    unsigned aoff = AOFF(lane), boff = BOFF(lane);

    // ---- load Q (64 rows) and K (128 rows): pure word copies ----
    #pragma unroll
    for (int i = 0; i < 2; i++) {
        int idx = tid + i * 256;            // 512 -> 64 rows x 8 uint4
        int row = idx >> 3, w4 = (idx & 7) << 2;
        size_t gbase = (size_t)(b * NT + q0 + row) * NW + h * 32 + w4;
        *(uint4*)&Qh[row * PW + w4] = *(const uint4*)&gQh[gbase];
        *(uint4*)&Ql[row * PW + w4] = *(const uint4*)&gQl[gbase];
    }
    #pragma unroll
    for (int i = 0; i < 4; i++) {
        int idx = tid + i * 256;            // 1024 -> 128 rows x 8 uint4
        int row = idx >> 3, w4 = (idx & 7) << 2;
        size_t gbase = (size_t)(b * NT + k0 + row) * NW + h * 32 + w4;
        *(uint4*)&Bh[row * PW + w4] = *(const uint4*)&gKh[gbase];
        *(uint4*)&Bl[row * PW + w4] = *(const uint4*)&gKl[gbase];
    }
    __syncthreads();

    // ---- QK GEMM: warp tile 32x32 ----
    float accK[2][4][4] = {};
    #pragma unroll
    for (int kw = 0; kw < 32; kw += 8) {
        unsigned ah[2][4], al[2][4];
        #pragma unroll
        for (int mt = 0; mt < 2; mt++) {
            unsigned base = (((wm * 32 + mt * 16) * PW + kw) << 2) + aoff;
            ldsm4(ah[mt][0], ah[mt][1], ah[mt][2], ah[mt][3], uQh + base);
            ldsm4(al[mt][0], al[mt][1], al[mt][2], al[mt][3], uQl + base);
        }
        #pragma unroll
        for (int pair = 0; pair < 2; pair++) {
            unsigned base = (((wn * 32 + pair * 16) * PW + kw) << 2) + boff;
            unsigned bhv[4], blv[4];
            ldsm4(bhv[0], bhv[1], bhv[2], bhv[3], uBh + base);
            ldsm4(blv[0], blv[1], blv[2], blv[3], uBl + base);
            #pragma unroll
            for (int half = 0; half < 2; half++) {
                int nt = pair * 2 + half;
                #pragma unroll
                for (int mt = 0; mt < 2; mt++) {
                    mma16(accK[mt][nt], ah[mt][0], ah[mt][1], ah[mt][2], ah[mt][3],
                          bhv[half*2], bhv[half*2+1]);
                    mma16(accK[mt][nt], ah[mt][0], ah[mt][1], ah[mt][2], ah[mt][3],
                          blv[half*2], blv[half*2+1]);
                    mma16(accK[mt][nt], al[mt][0], al[mt][1], al[mt][2], al[mt][3],
                          bhv[half*2], bhv[half*2+1]);
                }
            }
        }
    }

    int rbase = 960 + k0 - q0;   // >= 0 always; r = rbase + c, c = k + 63 - q
    const uint4 zero4 = make_uint4(0, 0, 0, 0);

    // ---- E chunk0: band cols 0..127 ----
    __syncthreads();
    #pragma unroll
    for (int i = 0; i < 4; i++) {
        int idx = tid + i * 256;
        int row = idx >> 3, w4 = (idx & 7) << 2;
        int r = rbase + row;
        size_t gbase = (size_t)r * NW + h * 32 + w4;
        *(uint4*)&Bh[row * PW + w4] = (r < NR) ? *(const uint4*)&gEh[gbase] : zero4;
        *(uint4*)&Bl[row * PW + w4] = (r < NR) ? *(const uint4*)&gEl[gbase] : zero4;
    }
    __syncthreads();
    {
        float accE[2][4][4] = {};
        #pragma unroll
        for (int kw = 0; kw < 32; kw += 8) {
            unsigned ah[2][4], al[2][4];
            #pragma unroll
            for (int mt = 0; mt < 2; mt++) {
                unsigned base = (((wm * 32 + mt * 16) * PW + kw) << 2) + aoff;
                ldsm4(ah[mt][0], ah[mt][1], ah[mt][2], ah[mt][3], uQh + base);
                ldsm4(al[mt][0], al[mt][1], al[mt][2], al[mt][3], uQl + base);
            }
            #pragma unroll
            for (int pair = 0; pair < 2; pair++) {
                unsigned base = (((wn * 32 + pair * 16) * PW + kw) << 2) + boff;
                unsigned bhv[4], blv[4];
                ldsm4(bhv[0], bhv[1], bhv[2], bhv[3], uBh + base);
                ldsm4(blv[0], blv[1], blv[2], blv[3], uBl + base);
                #pragma unroll
                for (int half = 0; half < 2; half++) {
                    int nt = pair * 2 + half;
                    #pragma unroll
                    for (int mt = 0; mt < 2; mt++) {
                        mma16(accE[mt][nt], ah[mt][0], ah[mt][1], ah[mt][2], ah[mt][3],
                              bhv[half*2], bhv[half*2+1]);
                        mma16(accE[mt][nt], ah[mt][0], ah[mt][1], ah[mt][2], ah[mt][3],
                              blv[half*2], blv[half*2+1]);
                        mma16(accE[mt][nt], al[mt][0], al[mt][1], al[mt][2], al[mt][3],
                              bhv[half*2], bhv[half*2+1]);
                    }
                }
            }
        }
        #pragma unroll
        for (int mt = 0; mt < 2; mt++)
            #pragma unroll
            for (int nt = 0; nt < 4; nt++) {
                int row = wm * 32 + mt * 16 + g;
                int col = wn * 32 + nt * 8 + t * 2;
                Gs[row * GSW + col]           = accE[mt][nt][0];
                Gs[row * GSW + col + 1]       = accE[mt][nt][1];
                Gs[(row + 8) * GSW + col]     = accE[mt][nt][2];
                Gs[(row + 8) * GSW + col + 1] = accE[mt][nt][3];
            }
    }

    // ---- E chunk1: band cols 128..191, warp n-width 16 ----
    __syncthreads();
    #pragma unroll
    for (int i = 0; i < 2; i++) {
        int idx = tid + i * 256;
        int row = idx >> 3, w4 = (idx & 7) << 2;
        int r = rbase + 128 + row;
        size_t gbase = (size_t)r * NW + h * 32 + w4;
        *(uint4*)&Bh[row * PW + w4] = (r < NR) ? *(const uint4*)&gEh[gbase] : zero4;
        *(uint4*)&Bl[row * PW + w4] = (r < NR) ? *(const uint4*)&gEl[gbase] : zero4;
    }
    __syncthreads();
    {
        float accF[2][2][4] = {};
        #pragma unroll
        for (int kw = 0; kw < 32; kw += 8) {
            unsigned ah[2][4], al[2][4];
            #pragma unroll
            for (int mt = 0; mt < 2; mt++) {
                unsigned base = (((wm * 32 + mt * 16) * PW + kw) << 2) + aoff;
                ldsm4(ah[mt][0], ah[mt][1], ah[mt][2], ah[mt][3], uQh + base);
                ldsm4(al[mt][0], al[mt][1], al[mt][2], al[mt][3], uQl + base);
            }
            unsigned base = (((wn * 16) * PW + kw) << 2) + boff;
            unsigned bhv[4], blv[4];
            ldsm4(bhv[0], bhv[1], bhv[2], bhv[3], uBh + base);
            ldsm4(blv[0], blv[1], blv[2], blv[3], uBl + base);
            #pragma unroll
            for (int half = 0; half < 2; half++) {
                #pragma unroll
                for (int mt = 0; mt < 2; mt++) {
                    mma16(accF[mt][half], ah[mt][0], ah[mt][1], ah[mt][2], ah[mt][3],
                          bhv[half*2], bhv[half*2+1]);
                    mma16(accF[mt][half], ah[mt][0], ah[mt][1], ah[mt][2], ah[mt][3],
                          blv[half*2], blv[half*2+1]);
                    mma16(accF[mt][half], al[mt][0], al[mt][1], al[mt][2], al[mt][3],
                          bhv[half*2], bhv[half*2+1]);
                }
            }
        }
        #pragma unroll
        for (int mt = 0; mt < 2; mt++)
            #pragma unroll
            for (int nt = 0; nt < 2; nt++) {
                int row = wm * 32 + mt * 16 + g;
                int col = 128 + wn * 16 + nt * 8 + t * 2;
                Gs[row * GSW + col]           = accF[mt][nt][0];
                Gs[row * GSW + col + 1]       = accF[mt][nt][1];
                Gs[(row + 8) * GSW + col]     = accF[mt][nt][2];
                Gs[(row + 8) * GSW + col + 1] = accF[mt][nt][3];
            }
    }
    __syncthreads();

    // ---- gather full raw scores ----
    #pragma unroll
    for (int mt = 0; mt < 2; mt++)
        #pragma unroll
        for (int nt = 0; nt < 4; nt++) {
            int kb = wn * 32 + nt * 8 + t * 2;
            #pragma unroll
            for (int r4 = 0; r4 < 4; r4++) {
                int q = wm * 32 + mt * 16 + g + ((r4 >= 2) ? 8 : 0);
                int k = kb + (r4 & 1);
                int c = k + 63 - q;
                accK[mt][nt][r4] = (accK[mt][nt][r4] + Gs[q * GSW + c]
                                    + gUK[bh * NT + k0 + k] + gVE[h * NR + rbase + c]) * 0.125f;
            }
        }

    // ---- per-tile row stats ----
    float mrow[2][2];
    #pragma unroll
    for (int mt = 0; mt < 2; mt++) {
        mrow[mt][0] = -1e30f; mrow[mt][1] = -1e30f;
        #pragma unroll
        for (int nt = 0; nt < 4; nt++) {
            mrow[mt][0] = fmaxf(mrow[mt][0], fmaxf(accK[mt][nt][0], accK[mt][nt][1]));
            mrow[mt][1] = fmaxf(mrow[mt][1], fmaxf(accK[mt][nt][2], accK[mt][nt][3]));
        }
        #pragma unroll
        for (int hf = 0; hf < 2; hf++) {
            mrow[mt][hf] = fmaxf(mrow[mt][hf], __shfl_xor_sync(0xffffffffu, mrow[mt][hf], 1));
            mrow[mt][hf] = fmaxf(mrow[mt][hf], __shfl_xor_sync(0xffffffffu, mrow[mt][hf], 2));
        }
    }
    if (t == 0) {
        #pragma unroll
        for (int mt = 0; mt < 2; mt++)
            #pragma unroll
            for (int hf = 0; hf < 2; hf++)
                redM[wn * 64 + wm * 32 + mt * 16 + g + hf * 8] = mrow[mt][hf];
    }
    __syncthreads();
    #pragma unroll
    for (int mt = 0; mt < 2; mt++)
        #pragma unroll
        for (int hf = 0; hf < 2; hf++) {
            int row = wm * 32 + mt * 16 + g + hf * 8;
            mrow[mt][hf] = fmaxf(fmaxf(redM[row], redM[64 + row]),
                                 fmaxf(redM[128 + row], redM[192 + row]));
        }

    float srow[2][2] = {};
    #pragma unroll
    for (int mt = 0; mt < 2; mt++)
        #pragma unroll
        for (int nt = 0; nt < 4; nt++) {
            accK[mt][nt][0] = __expf(accK[mt][nt][0] - mrow[mt][0]);
            accK[mt][nt][1] = __expf(accK[mt][nt][1] - mrow[mt][0]);
            accK[mt][nt][2] = __expf(accK[mt][nt][2] - mrow[mt][1]);
            accK[mt][nt][3] = __expf(accK[mt][nt][3] - mrow[mt][1]);
            srow[mt][0] += accK[mt][nt][0] + accK[mt][nt][1];
            srow[mt][1] += accK[mt][nt][2] + accK[mt][nt][3];
        }
    #pragma unroll
    for (int mt = 0; mt < 2; mt++)
        #pragma unroll
        for (int hf = 0; hf < 2; hf++) {
            srow[mt][hf] += __shfl_xor_sync(0xffffffffu, srow[mt][hf], 1);
            srow[mt][hf] += __shfl_xor_sync(0xffffffffu, srow[mt][hf], 2);
        }
    if (t == 0) {
        #pragma unroll
        for (int mt = 0; mt < 2; mt++)
            #pragma unroll
            for (int hf = 0; hf < 2; hf++)
                redL[wn * 64 + wm * 32 + mt * 16 + g + hf * 8] = srow[mt][hf];
    }
    __syncthreads();
    if (wn == 0 && t == 0) {
        #pragma unroll
        for (int mt = 0; mt < 2; mt++)
            #pragma unroll
            for (int hf = 0; hf < 2; hf++) {
                int row = wm * 32 + mt * 16 + g + hf * 8;
                size_t ri = (size_t)(bh * NT + q0 + row) * NKT + blockIdx.x;
                gPartM[ri] = mrow[mt][hf];
                gPartL[ri] = redL[row] + redL[64 + row] + redL[128 + row] + redL[192 + row];
            }
    }

    // ---- store exp values ----
    #pragma unroll
    for (int mt = 0; mt < 2; mt++)
        #pragma unroll
        for (int nt = 0; nt < 4; nt++) {
            int kb = wn * 32 + nt * 8 + t * 2;
            #pragma unroll
            for (int r4 = 0; r4 < 4; r4++) {
                int q = wm * 32 + mt * 16 + g + ((r4 >= 2) ? 8 : 0);
                int k = kb + (r4 & 1);
                gS[(size_t)(bh * NT + q0 + q) * NT + k0 + k] = accK[mt][nt][r4];
            }
        }
}

// ---------------- combine per-tile stats -> per-(row,tile) scales --------
__global__ void reduce_kernel() {
    int row = blockIdx.x * 256 + threadIdx.x;
    if (row >= NROWS) return;
    size_t base = (size_t)row * NKT;
    float m = -1e30f;
    float pm[NKT], pl[NKT];
    #pragma unroll
    for (int i = 0; i < NKT; i++) {
        pm[i] = gPartM[base + i];
        pl[i] = gPartL[base + i];
        m = fmaxf(m, pm[i]);
    }
    float l = 0.f;
    #pragma unroll
    for (int i = 0; i < NKT; i++) l += __expf(pm[i] - m) * pl[i];
    float inv = 1.f / l;
    #pragma unroll
    for (int i = 0; i < NKT; i++) gScale[base + i] = __expf(pm[i] - m) * inv;
}

// ---------------- O = P @ V: 128 thr, 4 warps, 32x32 warp tiles ----------
__global__ void pv_tc() {
    extern __shared__ unsigned sm[];
    unsigned* Ph  = sm;                   // 64*PW
    unsigned* Pl  = Ph + 64 * PW;
    unsigned* Vth = Pl + 64 * PW;         // 64*PW, [d][posword]
    unsigned* Vtl = Vth + 64 * PW;
    int tid = threadIdx.x;
    int warp = tid >> 5, lane = tid & 31;
    int wm = warp >> 1, wn = warp & 1;
    int g = lane >> 2, t = lane & 3;
    int bh = blockIdx.y, b = bh >> 3, h = bh & 7;
    int q0 = blockIdx.x * 64;
    float acc[2][4][4] = {};
    unsigned uPh = smaddr(Ph), uPl = smaddr(Pl), uVh = smaddr(Vth), uVl = smaddr(Vtl);
    unsigned aoff = AOFF(lane), boff = BOFF(lane);

    for (int kk0 = 0; kk0 < NT; kk0 += 64) {
        int kt8 = kk0 >> 7;
        #pragma unroll
        for (int i = 0; i < 8; i++) {
            int idx = tid + i * 128;
            int row = idx >> 4, c4 = (idx & 15) << 2;
            float sc = gScale[(size_t)(bh * NT + q0 + row) * NKT + kt8];
            float4 pv = *(const float4*)&gS[(size_t)(bh * NT + q0 + row) * NT + kk0 + c4];
            int w = c4 >> 1;
            unsigned h0, l0, h1, l1;
            cvt_pair2(pv.x * sc, pv.y * sc, h0, l0);
            cvt_pair2(pv.z * sc, pv.w * sc, h1, l1);
            *(uint2*)&Ph[row * PW + w] = make_uint2(h0, h1);
            *(uint2*)&Pl[row * PW + w] = make_uint2(l0, l1);
        }
        #pragma unroll
        for (int i = 0; i < 4; i++) {
            int u = tid + i * 128;
            int p = u >> 4, dg = (u & 15) << 2;
            const float* v0 = &gV[(size_t)(b * NT + kk0 + 2 * p) * ND + h * NDH + dg];
            const float* v1 = v0 + ND;
            float4 a = *(const float4*)v0;
            float4 c = *(const float4*)v1;
            unsigned hv, lv;
            cvt_pair2(a.x, c.x, hv, lv); Vth[(dg + 0) * PW + p] = hv; Vtl[(dg + 0) * PW + p] = lv;
            cvt_pair2(a.y, c.y, hv, lv); Vth[(dg + 1) * PW + p] = hv; Vtl[(dg + 1) * PW + p] = lv;
            cvt_pair2(a.z, c.z, hv, lv); Vth[(dg + 2) * PW + p] = hv; Vtl[(dg + 2) * PW + p] = lv;
            cvt_pair2(a.w, c.w, hv, lv); Vth[(dg + 3) * PW + p] = hv; Vtl[(dg + 3) * PW + p] = lv;
        }
        __syncthreads();
        #pragma unroll
        for (int kw = 0; kw < 32; kw += 8) {
            unsigned ah[2][4], al[2][4];
            #pragma unroll
            for (int mt = 0; mt < 2; mt++) {
                unsigned base = (((wm * 32 + mt * 16) * PW + kw) << 2) + aoff;
                ldsm4(ah[mt][0], ah[mt][1], ah[mt][2], ah[mt][3], uPh + base);
                ldsm4(al[mt][0], al[mt][1], al[mt][2], al[mt][3], uPl + base);
            }
            #pragma unroll
            for (int pair = 0; pair < 2; pair++) {
                unsigned base = (((wn * 32 + pair * 16) * PW + kw) << 2) + boff;
                unsigned bhv[4], blv[4];
                ldsm4(bhv[0], bhv[1], bhv[2], bhv[3], uVh + base);
                ldsm4(blv[0], blv[1], blv[2], blv[3], uVl + base);
                #pragma unroll
                for (int half = 0; half < 2; half++) {
                    int nt = pair * 2 + half;
                    #pragma unroll
                    for (int mt = 0; mt < 2; mt++) {
                        mma16(acc[mt][nt], ah[mt][0], ah[mt][1], ah[mt][2], ah[mt][3],
                              bhv[half*2], bhv[half*2+1]);
                        mma16(acc[mt][nt], ah[mt][0], ah[mt][1], ah[mt][2], ah[mt][3],
                              blv[half*2], blv[half*2+1]);
                        mma16(acc[mt][nt], al[mt][0], al[mt][1], al[mt][2], al[mt][3],
                              bhv[half*2], bhv[half*2+1]);
                    }
                }
            }
        }
        __syncthreads();
    }
    #pragma unroll
    for (int mt = 0; mt < 2; mt++)
        #pragma unroll
        for (int nt = 0; nt < 4; nt++) {
            int row = q0 + wm * 32 + mt * 16 + g;
            int col = wn * 32 + nt * 8 + t * 2;
            gO[(size_t)(b * NT + row) * ND + h * NDH + col]         = acc[mt][nt][0];
            gO[(size_t)(b * NT + row) * ND + h * NDH + col + 1]     = acc[mt][nt][1];
            gO[(size_t)(b * NT + row + 8) * ND + h * NDH + col]     = acc[mt][nt][2];
            gO[(size_t)(b * NT + row + 8) * ND + h * NDH + col + 1] = acc[mt][nt][3];
        }
}

// -------------------------------------------------------------------------
extern "C" void kernel_launch(void* const* d_in, const int* in_sizes, int n_in,
                              void* d_out, int out_size) {
    const float* query = (const float*)d_in[0];
    const float* key_  = (const float*)d_in[1];
    const float* value = (const float*)d_in[2];
    const float* Wq = (const float*)d_in[3];
    const float* bq = (const float*)d_in[4];
    const float* Wk = (const float*)d_in[5];
    const float* bk = (const float*)d_in[6];
    const float* Wv = (const float*)d_in[7];
    const float* bv = (const float*)d_in[8];
    const float* Wp = (const float*)d_in[9];
    const float* bp = (const float*)d_in[10];
    const float* Wo = (const float*)d_in[11];
    const float* bo = (const float*)d_in[12];
    const float* ub = (const float*)d_in[13];
    const float* vb = (const float*)d_in[14];
    float* out = (float*)d_out;

    unsigned *pQh, *pQl, *pKh, *pKl, *pEh, *pEl;
    float *pV, *pPE, *pO;
    cudaGetSymbolAddress((void**)&pQh, gQh);
    cudaGetSymbolAddress((void**)&pQl, gQl);
    cudaGetSymbolAddress((void**)&pKh, gKh);
    cudaGetSymbolAddress((void**)&pKl, gKl);
    cudaGetSymbolAddress((void**)&pEh, gEh);
    cudaGetSymbolAddress((void**)&pEl, gEl);
    cudaGetSymbolAddress((void**)&pV, gV);
    cudaGetSymbolAddress((void**)&pPE, gPE);
    cudaGetSymbolAddress((void**)&pO, gO);

    const int PROJ_SMEM   = (2 * 128 * PW + 2 * 64 * PW) * 4;                     // 55296
    const int SCORES_SMEM = (2 * 64 * PW + 2 * 128 * PW + 64 * GSW + 512) * 4;    // 107520
    const int PV_SMEM     = (4 * 64 * PW) * 4;                                    // 36864
    cudaFuncSetAttribute(proj_all,  cudaFuncAttributeMaxDynamicSharedMemorySize, PROJ_SMEM);
    cudaFuncSetAttribute(proj_out,  cudaFuncAttributeMaxDynamicSharedMemorySize, PROJ_SMEM);
    cudaFuncSetAttribute(scores_tc, cudaFuncAttributeMaxDynamicSharedMemorySize, SCORES_SMEM);
    cudaFuncSetAttribute(pv_tc,     cudaFuncAttributeMaxDynamicSharedMemorySize, PV_SMEM);

    ProjArgs pa;
    pa.A[0] = query; pa.W[0] = Wq; pa.bias[0] = bq; pa.M[0] = NM;
    pa.Ch[0] = pQh;  pa.Cl[0] = pQl; pa.Cf[0] = 0;  pa.split[0] = 1;
    pa.A[1] = key_;  pa.W[1] = Wk; pa.bias[1] = bk; pa.M[1] = NM;
    pa.Ch[1] = pKh;  pa.Cl[1] = pKl; pa.Cf[1] = 0;  pa.split[1] = 1;
    pa.A[2] = value; pa.W[2] = Wv; pa.bias[2] = bv; pa.M[2] = NM;
    pa.Ch[2] = 0;    pa.Cl[2] = 0;   pa.Cf[2] = pV; pa.split[2] = 0;
    pa.A[3] = pPE;   pa.W[3] = Wp; pa.bias[3] = bp; pa.M[3] = NR;
    pa.Ch[3] = pEh;  pa.Cl[3] = pEl; pa.Cf[3] = 0;  pa.split[3] = 1;

    pe_kernel<<<NR, 256>>>();
    proj_all<<<896, 256, PROJ_SMEM>>>(pa);
    ukve_kernel<<<6143, 256>>>(ub, vb);
    scores_tc<<<dim3(8, 16, 32), 256, SCORES_SMEM>>>();
    reduce_kernel<<<128, 256>>>();
    pv_tc<<<dim3(16, 32), 128, PV_SMEM>>>();
    proj_out<<<dim3(8, 32), 256, PROJ_SMEM>>>(pO, Wo, bo, out, NM);
}